// round 12
// baseline (speedup 1.0000x reference)
#include <cuda_runtime.h>
#include <cuda_bf16.h>
#include <cstdint>
#include <math.h>

// Problem dims (fixed by the reference)
#define TT 4096
#define CC 1024
#define HF 4096
#define NH 16
#define HD 64

// ---------------- scratch (device globals: allocation-free) ----------------
__device__ float g_xn [(size_t)TT * CC];
__device__ float g_qkv[(size_t)TT * 3 * CC];
__device__ float g_y  [(size_t)TT * CC];
__device__ float g_x1 [(size_t)TT * CC];
__device__ float g_h1 [(size_t)TT * HF];
__device__ float g_h3 [(size_t)TT * HF];
// pre-split bf16 Q/K/V (hi + lo residual), Q pre-scaled by log2e/8.
__device__ uint4 g_qh[(size_t)TT * CC / 8];
__device__ uint4 g_ql[(size_t)TT * CC / 8];
__device__ uint4 g_kh[(size_t)TT * CC / 8];
__device__ uint4 g_kl[(size_t)TT * CC / 8];
__device__ uint4 g_vh[(size_t)TT * CC / 8];
__device__ uint4 g_vl[(size_t)TT * CC / 8];

// ================= helpers =================
__device__ __forceinline__ uint32_t smem_u32(const void* p) {
    uint32_t a;
    asm("{ .reg .u64 t; cvta.to.shared.u64 t, %1; cvt.u32.u64 %0, t; }" : "=r"(a) : "l"(p));
    return a;
}
__device__ __forceinline__ uint32_t cvt2(float a, float b) {
    uint32_t r;
    asm("cvt.rn.satfinite.bf16x2.f32 %0, %1, %2;" : "=r"(r) : "f"(b), "f"(a));
    return r;
}
__device__ __forceinline__ float ex2(float x) {
    float r;
    asm("ex2.approx.f32 %0, %1;" : "=f"(r) : "f"(x));
    return r;
}
__device__ __forceinline__ void mma_bf16(float* c, const uint32_t* a, const uint32_t* b) {
    asm volatile(
        "mma.sync.aligned.m16n8k16.row.col.f32.bf16.bf16.f32 "
        "{%0,%1,%2,%3}, {%4,%5,%6,%7}, {%8,%9}, {%0,%1,%2,%3};"
        : "+f"(c[0]), "+f"(c[1]), "+f"(c[2]), "+f"(c[3])
        : "r"(a[0]), "r"(a[1]), "r"(a[2]), "r"(a[3]), "r"(b[0]), "r"(b[1]));
}
__device__ __forceinline__ void ldsm_x4(uint32_t addr, uint32_t& b0, uint32_t& b1,
                                        uint32_t& b2, uint32_t& b3) {
    asm volatile("ldmatrix.sync.aligned.m8n8.x4.shared.b16 {%0,%1,%2,%3}, [%4];"
                 : "=r"(b0), "=r"(b1), "=r"(b2), "=r"(b3) : "r"(addr));
}
__device__ __forceinline__ void ldsm_x4_trans(uint32_t addr, uint32_t& b0, uint32_t& b1,
                                              uint32_t& b2, uint32_t& b3) {
    asm volatile("ldmatrix.sync.aligned.m8n8.x4.trans.shared.b16 {%0,%1,%2,%3}, [%4];"
                 : "=r"(b0), "=r"(b1), "=r"(b2), "=r"(b3) : "r"(addr));
}
__device__ __forceinline__ void split4(float4 v, uint2& h, uint2& l) {
    h.x = cvt2(v.x, v.y);
    h.y = cvt2(v.z, v.w);
    float r0 = v.x - __uint_as_float(h.x << 16);
    float r1 = v.y - __uint_as_float(h.x & 0xFFFF0000u);
    float r2 = v.z - __uint_as_float(h.y << 16);
    float r3 = v.w - __uint_as_float(h.y & 0xFFFF0000u);
    l.x = cvt2(r0, r1);
    l.y = cvt2(r2, r3);
}
__device__ __forceinline__ void cpa16(uint32_t dst, const void* src) {
    asm volatile("cp.async.cg.shared.global [%0], [%1], 16;" :: "r"(dst), "l"(src) : "memory");
}
#define CP_COMMIT() asm volatile("cp.async.commit_group;" ::: "memory")
#define CP_WAIT0()  asm volatile("cp.async.wait_group 0;" ::: "memory")

// ================= bf16-split tensor-core GEMM (R9 structure, optional fused SwiGLU) ====
// C[M,N] = op(A)[M,K] * B[N,K]^T (+ add).  ACT: op(A) = silu(A) * A2 elementwise.
#define TROW 80
#define TILE_BYTES (128 * TROW)
#define STAGE_BYTES (4 * TILE_BYTES)
#define GEMM_SMEM (2 * STAGE_BYTES)

template<bool ACT>
__global__ void __launch_bounds__(256)
gemm_bf16s(const float* __restrict__ A, const float* __restrict__ A2,
           const float* __restrict__ B,
           float* __restrict__ C, int M, int N, int K,
           const float* __restrict__ add) {
    extern __shared__ char smem[];
    const uint32_t sbase = smem_u32(smem);

    const int tid  = threadIdx.x;
    const int warp = tid >> 5;
    const int lane = tid & 31;
    const int g = lane >> 2;
    const int t = lane & 3;
    const int blk = lane >> 3, lr = lane & 7;
    const int wm = warp >> 2;
    const int wn = warp & 3;
    const int m0 = wm * 64;
    const int n0 = wn * 32;
    const int bm = blockIdx.y * 128;
    const int bn = blockIdx.x * 128;

    // ldmatrix lane offsets
    const uint32_t aoff = (uint32_t)((blk & 1) * 8 + lr) * TROW + (uint32_t)(blk >> 1) * 16;
    const uint32_t boff = (uint32_t)((lane >> 4) * 8 + lr) * TROW + (uint32_t)(blk & 1) * 16;

    float acc[4][4][4];
    #pragma unroll
    for (int i = 0; i < 4; i++)
        #pragma unroll
        for (int j = 0; j < 4; j++)
            #pragma unroll
            for (int r = 0; r < 4; r++) acc[i][j][r] = 0.f;

    float4 va[4], vb[4];
    const int nc = K >> 5;

    auto loadA = [&](int row, int q, int k0) -> float4 {
        float4 v = *(const float4*)(A + (size_t)(bm + row) * K + k0 + q * 4);
        if (ACT) {
            float4 u = *(const float4*)(A2 + (size_t)(bm + row) * K + k0 + q * 4);
            v.x = v.x / (1.f + __expf(-v.x)) * u.x;
            v.y = v.y / (1.f + __expf(-v.y)) * u.y;
            v.z = v.z / (1.f + __expf(-v.z)) * u.z;
            v.w = v.w / (1.f + __expf(-v.w)) * u.w;
        }
        return v;
    };

    // ---- prologue: load + store chunk 0 (each thread: one A slot AND one B slot per u)
    {
        #pragma unroll
        for (int u = 0; u < 4; u++) {
            int s = tid + u * 256;
            int row = s >> 3, q = s & 7;
            va[u] = loadA(row, q, 0);
            vb[u] = *(const float4*)(B + (size_t)(bn + row) * K + q * 4);
        }
        char* base = smem;
        #pragma unroll
        for (int u = 0; u < 4; u++) {
            int s = tid + u * 256;
            int row = s >> 3, q = s & 7;
            uint32_t off = (uint32_t)row * TROW + (uint32_t)q * 8;
            uint2 h, l;
            split4(va[u], h, l);
            *(uint2*)(base + off)              = h;
            *(uint2*)(base + TILE_BYTES + off) = l;
            split4(vb[u], h, l);
            *(uint2*)(base + 2 * TILE_BYTES + off) = h;
            *(uint2*)(base + 3 * TILE_BYTES + off) = l;
        }
    }
    __syncthreads();

    for (int c = 0; c < nc; c++) {
        const int cur = c & 1;
        const bool more = (c + 1 < nc);

        if (more) {
            int k0 = (c + 1) << 5;
            #pragma unroll
            for (int u = 0; u < 4; u++) {
                int s = tid + u * 256;
                int row = s >> 3, q = s & 7;
                va[u] = loadA(row, q, k0);
                vb[u] = *(const float4*)(B + (size_t)(bn + row) * K + k0 + q * 4);
            }
        }

        // ---- compute on stage cur (ldmatrix fragments)
        {
            const uint32_t stg = sbase + (uint32_t)cur * STAGE_BYTES;

            uint32_t bh[2][2][4], bl[2][2][4];
            #pragma unroll
            for (int j2 = 0; j2 < 2; j2++)
                #pragma unroll
                for (int ks = 0; ks < 2; ks++) {
                    uint32_t ad = stg + 2 * TILE_BYTES +
                                  (uint32_t)(n0 + j2 * 16) * TROW + boff + ks * 32;
                    ldsm_x4(ad, bh[j2][ks][0], bh[j2][ks][1], bh[j2][ks][2], bh[j2][ks][3]);
                    ldsm_x4(ad + TILE_BYTES, bl[j2][ks][0], bl[j2][ks][1], bl[j2][ks][2], bl[j2][ks][3]);
                }

            #pragma unroll
            for (int i = 0; i < 4; i++) {
                uint32_t ad = stg + (uint32_t)(m0 + i * 16) * TROW + aoff;
                uint32_t ah0[4], ah1[4], al0[4], al1[4];
                ldsm_x4(ad,                     ah0[0], ah0[1], ah0[2], ah0[3]);
                ldsm_x4(ad + 32,                ah1[0], ah1[1], ah1[2], ah1[3]);
                ldsm_x4(ad + TILE_BYTES,        al0[0], al0[1], al0[2], al0[3]);
                ldsm_x4(ad + TILE_BYTES + 32,   al1[0], al1[1], al1[2], al1[3]);
                #pragma unroll
                for (int j2 = 0; j2 < 2; j2++)
                    #pragma unroll
                    for (int jj = 0; jj < 2; jj++) {
                        float* cc = acc[i][j2 * 2 + jj];
                        mma_bf16(cc, ah0, &bh[j2][0][jj * 2]);
                        mma_bf16(cc, al0, &bh[j2][0][jj * 2]);
                        mma_bf16(cc, ah0, &bl[j2][0][jj * 2]);
                        mma_bf16(cc, ah1, &bh[j2][1][jj * 2]);
                        mma_bf16(cc, al1, &bh[j2][1][jj * 2]);
                        mma_bf16(cc, ah1, &bl[j2][1][jj * 2]);
                    }
            }
        }

        if (more) {
            char* base = smem + (cur ^ 1) * STAGE_BYTES;
            #pragma unroll
            for (int u = 0; u < 4; u++) {
                int s = tid + u * 256;
                int row = s >> 3, q = s & 7;
                uint32_t off = (uint32_t)row * TROW + (uint32_t)q * 8;
                uint2 h, l;
                split4(va[u], h, l);
                *(uint2*)(base + off)              = h;
                *(uint2*)(base + TILE_BYTES + off) = l;
                split4(vb[u], h, l);
                *(uint2*)(base + 2 * TILE_BYTES + off) = h;
                *(uint2*)(base + 3 * TILE_BYTES + off) = l;
            }
        }
        __syncthreads();
    }

    // ---- epilogue
    #pragma unroll
    for (int i = 0; i < 4; i++) {
        size_t r0 = (size_t)(bm + m0 + i * 16 + g);
        size_t r1 = r0 + 8;
        #pragma unroll
        for (int j = 0; j < 4; j++) {
            int col = bn + n0 + j * 8 + t * 2;
            float2 v0 = make_float2(acc[i][j][0], acc[i][j][1]);
            float2 v1 = make_float2(acc[i][j][2], acc[i][j][3]);
            if (add) {
                float2 a0 = *(const float2*)(add + r0 * N + col);
                float2 a1 = *(const float2*)(add + r1 * N + col);
                v0.x += a0.x; v0.y += a0.y;
                v1.x += a1.x; v1.y += a1.y;
            }
            *(float2*)(C + r0 * N + col) = v0;
            *(float2*)(C + r1 * N + col) = v1;
        }
    }
}

// ================= QKV pre-split: fp32 qkv -> bf16 hi/lo (Q scaled by log2e/8) =========
__global__ void __launch_bounds__(256)
split_qkv(const float* __restrict__ qkv,
          uint4* __restrict__ qh, uint4* __restrict__ ql,
          uint4* __restrict__ kh, uint4* __restrict__ kl,
          uint4* __restrict__ vh, uint4* __restrict__ vl) {
    const float qs = 1.4426950408889634f * 0.125f;
    int i = blockIdx.x * blockDim.x + threadIdx.x;
    int r  = i >> 7;
    int c8 = (i & 127) * 8;
    const float* base = qkv + (size_t)r * 3 * CC + c8;

    float4 a = *(const float4*)(base);
    float4 b = *(const float4*)(base + 4);
    a.x *= qs; a.y *= qs; a.z *= qs; a.w *= qs;
    b.x *= qs; b.y *= qs; b.z *= qs; b.w *= qs;
    uint2 h0, l0, h1, l1;
    split4(a, h0, l0); split4(b, h1, l1);
    qh[i] = make_uint4(h0.x, h0.y, h1.x, h1.y);
    ql[i] = make_uint4(l0.x, l0.y, l1.x, l1.y);

    a = *(const float4*)(base + CC);
    b = *(const float4*)(base + CC + 4);
    split4(a, h0, l0); split4(b, h1, l1);
    kh[i] = make_uint4(h0.x, h0.y, h1.x, h1.y);
    kl[i] = make_uint4(l0.x, l0.y, l1.x, l1.y);

    a = *(const float4*)(base + 2 * CC);
    b = *(const float4*)(base + 2 * CC + 4);
    split4(a, h0, l0); split4(b, h1, l1);
    vh[i] = make_uint4(h0.x, h0.y, h1.x, h1.y);
    vl[i] = make_uint4(l0.x, l0.y, l1.x, l1.y);
}

// ================= MMA flash attention (unchanged — 356-360us measured) =========
#define ASTR 144
#define QLSM (128 * ASTR)
#define ABUF0 (2 * QLSM)
#define KVT (64 * ASTR)
#define ABUFB (4 * KVT)
#define ATTN_SMEM (ABUF0 + 2 * ABUFB)  // 110592

__global__ void __launch_bounds__(256, 2)
attn_mma(const char* __restrict__ qhc, const char* __restrict__ qlc,
         const char* __restrict__ khc, const char* __restrict__ klc,
         const char* __restrict__ vhc, const char* __restrict__ vlc,
         float* __restrict__ y) {
    extern __shared__ char sm[];
    const uint32_t sb = smem_u32(sm);
    const int tid  = threadIdx.x;
    const int w    = tid >> 5;
    const int lane = tid & 31;
    const int g = lane >> 2, t = lane & 3;
    const int qt = 31 - (int)blockIdx.x;
    const int h  = blockIdx.y;
    const int q0 = qt * 128;
    const int qko = h * HD;

    const int cr = tid >> 3;
    const int ch = tid & 7;
    const size_t rowb = (size_t)2 * CC;

    #pragma unroll
    for (int u = 0; u < 8; u++) {
        int r = (u & 3) * 32 + cr;
        const char* src = ((u >> 2) ? qlc : qhc) + (size_t)(q0 + r) * rowb + qko * 2 + ch * 16;
        cpa16(sb + (u >> 2) * QLSM + (uint32_t)r * ASTR + ch * 16, src);
    }
    #pragma unroll
    for (int u = 0; u < 8; u++) {
        int r = (u & 1) * 32 + cr;
        const char* tp = (u < 2) ? khc : (u < 4) ? klc : (u < 6) ? vhc : vlc;
        const char* src = tp + (size_t)r * rowb + qko * 2 + ch * 16;
        cpa16(sb + ABUF0 + (u >> 1) * KVT + (uint32_t)r * ASTR + ch * 16, src);
    }
    CP_COMMIT();
    CP_WAIT0();
    __syncthreads();

    const int blk = lane >> 3, lr = lane & 7;
    uint32_t qfh[4][4], qfl[4][4];
    {
        uint32_t qa = sb + (uint32_t)(w * 16 + (blk & 1) * 8 + lr) * ASTR + (uint32_t)(blk >> 1) * 16;
        #pragma unroll
        for (int ks = 0; ks < 4; ks++) {
            ldsm_x4(qa + ks * 32,        qfh[ks][0], qfh[ks][1], qfh[ks][2], qfh[ks][3]);
            ldsm_x4(qa + QLSM + ks * 32, qfl[ks][0], qfl[ks][1], qfl[ks][2], qfl[ks][3]);
        }
    }

    float O[8][4];
    #pragma unroll
    for (int nf = 0; nf < 8; nf++)
        #pragma unroll
        for (int r = 0; r < 4; r++) O[nf][r] = 0.f;
    float l0 = 0.f, l1 = 0.f;

    const int nk = 2 * qt + 2;
    const int r0g = q0 + w * 16 + g;
    const uint32_t ldsmV_off = (uint32_t)((blk & 1) * 8 + lr) * ASTR + (uint32_t)(blk >> 1) * 16;
    const uint32_t ldsmK_off = (uint32_t)(((lane >> 4) << 3) | lr) * ASTR + (uint32_t)((blk & 1) * 16);

    for (int kt = 0; kt < nk; kt++) {
        const uint32_t kb = ABUF0 + (uint32_t)(kt & 1) * ABUFB;
        const bool more = (kt + 1 < nk);

        if (more) {
            int k0n = (kt + 1) * 64;
            uint32_t nb = sb + ABUF0 + (uint32_t)((kt + 1) & 1) * ABUFB;
            #pragma unroll
            for (int u = 0; u < 8; u++) {
                int r = (u & 1) * 32 + cr;
                const char* tp = (u < 2) ? khc : (u < 4) ? klc : (u < 6) ? vhc : vlc;
                const char* src = tp + (size_t)(k0n + r) * rowb + qko * 2 + ch * 16;
                cpa16(nb + (u >> 1) * KVT + (uint32_t)r * ASTR + ch * 16, src);
            }
            CP_COMMIT();
        }

        float S[8][4];
        #pragma unroll
        for (int nf = 0; nf < 8; nf++)
            #pragma unroll
            for (int r = 0; r < 4; r++) S[nf][r] = 0.f;

        {
            const uint32_t kh = sb + kb + ldsmK_off;
            #pragma unroll
            for (int ks = 0; ks < 4; ks++) {
                #pragma unroll
                for (int nfp = 0; nfp < 4; nfp++) {
                    uint32_t a = kh + (uint32_t)(nfp * 16) * ASTR + (uint32_t)(ks * 32);
                    uint32_t h0, h1, h2, h3, l0r, l1r, l2r, l3r;
                    ldsm_x4(a, h0, h1, h2, h3);
                    ldsm_x4(a + KVT, l0r, l1r, l2r, l3r);
                    uint32_t bh0[2] = {h0, h1}, bh1[2] = {h2, h3};
                    uint32_t bl0[2] = {l0r, l1r}, bl1[2] = {l2r, l3r};
                    mma_bf16(S[2 * nfp],     qfh[ks], bh0);
                    mma_bf16(S[2 * nfp],     qfl[ks], bh0);
                    mma_bf16(S[2 * nfp],     qfh[ks], bl0);
                    mma_bf16(S[2 * nfp + 1], qfh[ks], bh1);
                    mma_bf16(S[2 * nfp + 1], qfl[ks], bh1);
                    mma_bf16(S[2 * nfp + 1], qfh[ks], bl1);
                }
            }
        }

        if (kt >= 2 * qt) {
            int k0 = kt * 64;
            #pragma unroll
            for (int nf = 0; nf < 8; nf++) {
                int c = k0 + nf * 8 + 2 * t;
                if (c     > r0g)     S[nf][0] = -1e30f;
                if (c + 1 > r0g)     S[nf][1] = -1e30f;
                if (c     > r0g + 8) S[nf][2] = -1e30f;
                if (c + 1 > r0g + 8) S[nf][3] = -1e30f;
            }
        }

        #pragma unroll
        for (int nf = 0; nf < 8; nf++) {
            S[nf][0] = ex2(S[nf][0]);
            S[nf][1] = ex2(S[nf][1]);
            S[nf][2] = ex2(S[nf][2]);
            S[nf][3] = ex2(S[nf][3]);
            l0 += S[nf][0] + S[nf][1];
            l1 += S[nf][2] + S[nf][3];
        }

        {
            const uint32_t vh = sb + kb + 2 * KVT + ldsmV_off;
            #pragma unroll
            for (int ks = 0; ks < 4; ks++) {
                float p00 = S[2 * ks][0], p01 = S[2 * ks][1];
                float p02 = S[2 * ks][2], p03 = S[2 * ks][3];
                float p10 = S[2 * ks + 1][0], p11 = S[2 * ks + 1][1];
                float p12 = S[2 * ks + 1][2], p13 = S[2 * ks + 1][3];
                uint32_t pah[4], pal[4];
                pah[0] = cvt2(p00, p01);
                pah[1] = cvt2(p02, p03);
                pah[2] = cvt2(p10, p11);
                pah[3] = cvt2(p12, p13);
                pal[0] = cvt2(p00 - __uint_as_float(pah[0] << 16),
                              p01 - __uint_as_float(pah[0] & 0xFFFF0000u));
                pal[1] = cvt2(p02 - __uint_as_float(pah[1] << 16),
                              p03 - __uint_as_float(pah[1] & 0xFFFF0000u));
                pal[2] = cvt2(p10 - __uint_as_float(pah[2] << 16),
                              p11 - __uint_as_float(pah[2] & 0xFFFF0000u));
                pal[3] = cvt2(p12 - __uint_as_float(pah[3] << 16),
                              p13 - __uint_as_float(pah[3] & 0xFFFF0000u));

                uint32_t ka = vh + (uint32_t)(ks * 16) * ASTR;
                #pragma unroll
                for (int np = 0; np < 4; np++) {
                    uint32_t a = ka + (uint32_t)np * 32;
                    uint32_t b0, b1, b2, b3;
                    ldsm_x4_trans(a, b0, b1, b2, b3);
                    uint32_t bb0[2] = {b0, b1}, bb1[2] = {b2, b3};
                    mma_bf16(O[2 * np],     pah, bb0);
                    mma_bf16(O[2 * np + 1], pah, bb1);
                    mma_bf16(O[2 * np],     pal, bb0);
                    mma_bf16(O[2 * np + 1], pal, bb1);
                    ldsm_x4_trans(a + KVT, b0, b1, b2, b3);
                    uint32_t cb0[2] = {b0, b1}, cb1[2] = {b2, b3};
                    mma_bf16(O[2 * np],     pah, cb0);
                    mma_bf16(O[2 * np + 1], pah, cb1);
                }
            }
        }

        if (more) CP_WAIT0();
        __syncthreads();
    }

    l0 += __shfl_xor_sync(0xFFFFFFFFu, l0, 1);
    l0 += __shfl_xor_sync(0xFFFFFFFFu, l0, 2);
    l1 += __shfl_xor_sync(0xFFFFFFFFu, l1, 1);
    l1 += __shfl_xor_sync(0xFFFFFFFFu, l1, 2);
    float i0 = 1.f / l0, i1 = 1.f / l1;
    #pragma unroll
    for (int nf = 0; nf < 8; nf++) {
        int col = qko + nf * 8 + 2 * t;
        *(float2*)(y + (size_t)r0g * CC + col) =
            make_float2(O[nf][0] * i0, O[nf][1] * i0);
        *(float2*)(y + (size_t)(r0g + 8) * CC + col) =
            make_float2(O[nf][2] * i1, O[nf][3] * i1);
    }
}

// ---------------- RMSNorm: one block per row ----------------
__global__ void rmsnorm_kernel(const float* __restrict__ x,
                               const float* __restrict__ w,
                               float* __restrict__ o, int C) {
    int row = blockIdx.x;
    const float* xr = x + (size_t)row * C;
    float s = 0.f;
    for (int i = threadIdx.x; i < C; i += blockDim.x) {
        float v = xr[i];
        s += v * v;
    }
    __shared__ float red[32];
    #pragma unroll
    for (int off = 16; off; off >>= 1) s += __shfl_down_sync(0xFFFFFFFFu, s, off);
    if ((threadIdx.x & 31) == 0) red[threadIdx.x >> 5] = s;
    __syncthreads();
    if (threadIdx.x < 32) {
        float v = (threadIdx.x < (blockDim.x >> 5)) ? red[threadIdx.x] : 0.f;
        #pragma unroll
        for (int off = 16; off; off >>= 1) v += __shfl_down_sync(0xFFFFFFFFu, v, off);
        if (threadIdx.x == 0) red[0] = v;
    }
    __syncthreads();
    float inv = rsqrtf(red[0] / (float)C + 1e-6f);
    for (int i = threadIdx.x; i < C; i += blockDim.x)
        o[(size_t)row * C + i] = xr[i] * inv * w[i];
}

// ---------------- launch ----------------
extern "C" void kernel_launch(void* const* d_in, const int* in_sizes, int n_in,
                              void* d_out, int out_size) {
    const float* x           = (const float*)d_in[0];
    const float* attn_norm_w = (const float*)d_in[1];
    const float* ffn_norm_w  = (const float*)d_in[2];
    const float* c_attn_w    = (const float*)d_in[3];
    const float* c_proj_w    = (const float*)d_in[4];
    const float* w1          = (const float*)d_in[5];
    const float* w2          = (const float*)d_in[6];
    const float* w3          = (const float*)d_in[7];
    float* out = (float*)d_out;

    float *xn, *qkv, *yb, *x1, *h1, *h3;
    cudaGetSymbolAddress((void**)&xn,  g_xn);
    cudaGetSymbolAddress((void**)&qkv, g_qkv);
    cudaGetSymbolAddress((void**)&yb,  g_y);
    cudaGetSymbolAddress((void**)&x1,  g_x1);
    cudaGetSymbolAddress((void**)&h1,  g_h1);
    cudaGetSymbolAddress((void**)&h3,  g_h3);
    void *qh, *ql, *kh, *kl, *vh, *vl;
    cudaGetSymbolAddress(&qh, g_qh);
    cudaGetSymbolAddress(&ql, g_ql);
    cudaGetSymbolAddress(&kh, g_kh);
    cudaGetSymbolAddress(&kl, g_kl);
    cudaGetSymbolAddress(&vh, g_vh);
    cudaGetSymbolAddress(&vl, g_vl);

    cudaFuncSetAttribute(gemm_bf16s<false>, cudaFuncAttributeMaxDynamicSharedMemorySize, GEMM_SMEM);
    cudaFuncSetAttribute(gemm_bf16s<true>,  cudaFuncAttributeMaxDynamicSharedMemorySize, GEMM_SMEM);
    cudaFuncSetAttribute(attn_mma, cudaFuncAttributeMaxDynamicSharedMemorySize, ATTN_SMEM);

    // 1) xn = rmsnorm(x, attn_norm_w)
    rmsnorm_kernel<<<TT, 256>>>(x, attn_norm_w, xn, CC);

    // 2) qkv = xn @ c_attn_w^T       [4096, 3072]
    gemm_bf16s<false><<<dim3(3 * CC / 128, TT / 128), 256, GEMM_SMEM>>>(
        xn, nullptr, c_attn_w, qkv, TT, 3 * CC, CC, nullptr);

    // 3) pre-split qkv into bf16 hi/lo tensors (Q pre-scaled)
    split_qkv<<<TT * CC / 8 / 256, 256>>>(qkv, (uint4*)qh, (uint4*)ql,
                                          (uint4*)kh, (uint4*)kl, (uint4*)vh, (uint4*)vl);

    // 4) y = causal_attention       [4096, 1024]
    attn_mma<<<dim3(TT / 128, NH), 256, ATTN_SMEM>>>(
        (const char*)qh, (const char*)ql, (const char*)kh,
        (const char*)kl, (const char*)vh, (const char*)vl, yb);

    // 5) x1 = y @ c_proj_w^T + x
    gemm_bf16s<false><<<dim3(CC / 128, TT / 128), 256, GEMM_SMEM>>>(
        yb, nullptr, c_proj_w, x1, TT, CC, CC, x);

    // 6) xn = rmsnorm(x1, ffn_norm_w)
    rmsnorm_kernel<<<TT, 256>>>(x1, ffn_norm_w, xn, CC);

    // 7) h1 = xn @ w1^T ; h3 = xn @ w3^T
    gemm_bf16s<false><<<dim3(HF / 128, TT / 128), 256, GEMM_SMEM>>>(
        xn, nullptr, w1, h1, TT, HF, CC, nullptr);
    gemm_bf16s<false><<<dim3(HF / 128, TT / 128), 256, GEMM_SMEM>>>(
        xn, nullptr, w3, h3, TT, HF, CC, nullptr);

    // 8) out = (silu(h1)*h3) @ w2^T + x1   (SwiGLU fused into A-load)
    gemm_bf16s<true><<<dim3(CC / 128, TT / 128), 256, GEMM_SMEM>>>(
        h1, h3, w2, out, TT, CC, HF, x1);
}

// round 13
// speedup vs baseline: 1.9159x; 1.9159x over previous
#include <cuda_runtime.h>
#include <cuda_bf16.h>
#include <cstdint>
#include <math.h>

// Problem dims (fixed by the reference)
#define TT 4096
#define CC 1024
#define HF 4096
#define NH 16
#define HD 64

// ---------------- scratch (device globals: allocation-free) ----------------
__device__ float g_xn [(size_t)TT * CC];
__device__ float g_qkv[(size_t)TT * 3 * CC];
__device__ float g_y  [(size_t)TT * CC];
__device__ float g_x1 [(size_t)TT * CC];
__device__ float g_h1 [(size_t)TT * HF];
// pre-split bf16 Q/K/V (hi + lo residual), Q pre-scaled by log2e/8.
__device__ uint4 g_qh[(size_t)TT * CC / 8];
__device__ uint4 g_ql[(size_t)TT * CC / 8];
__device__ uint4 g_kh[(size_t)TT * CC / 8];
__device__ uint4 g_kl[(size_t)TT * CC / 8];
__device__ uint4 g_vh[(size_t)TT * CC / 8];
__device__ uint4 g_vl[(size_t)TT * CC / 8];

// ================= helpers =================
__device__ __forceinline__ uint32_t smem_u32(const void* p) {
    uint32_t a;
    asm("{ .reg .u64 t; cvta.to.shared.u64 t, %1; cvt.u32.u64 %0, t; }" : "=r"(a) : "l"(p));
    return a;
}
__device__ __forceinline__ uint32_t cvt2(float a, float b) {
    uint32_t r;
    asm("cvt.rn.satfinite.bf16x2.f32 %0, %1, %2;" : "=r"(r) : "f"(b), "f"(a));
    return r;
}
__device__ __forceinline__ float ex2(float x) {
    float r;
    asm("ex2.approx.f32 %0, %1;" : "=f"(r) : "f"(x));
    return r;
}
__device__ __forceinline__ void mma_bf16(float* c, const uint32_t* a, const uint32_t* b) {
    asm volatile(
        "mma.sync.aligned.m16n8k16.row.col.f32.bf16.bf16.f32 "
        "{%0,%1,%2,%3}, {%4,%5,%6,%7}, {%8,%9}, {%0,%1,%2,%3};"
        : "+f"(c[0]), "+f"(c[1]), "+f"(c[2]), "+f"(c[3])
        : "r"(a[0]), "r"(a[1]), "r"(a[2]), "r"(a[3]), "r"(b[0]), "r"(b[1]));
}
__device__ __forceinline__ void ldsm_x4(uint32_t addr, uint32_t& b0, uint32_t& b1,
                                        uint32_t& b2, uint32_t& b3) {
    asm volatile("ldmatrix.sync.aligned.m8n8.x4.shared.b16 {%0,%1,%2,%3}, [%4];"
                 : "=r"(b0), "=r"(b1), "=r"(b2), "=r"(b3) : "r"(addr));
}
__device__ __forceinline__ void ldsm_x4_trans(uint32_t addr, uint32_t& b0, uint32_t& b1,
                                              uint32_t& b2, uint32_t& b3) {
    asm volatile("ldmatrix.sync.aligned.m8n8.x4.trans.shared.b16 {%0,%1,%2,%3}, [%4];"
                 : "=r"(b0), "=r"(b1), "=r"(b2), "=r"(b3) : "r"(addr));
}
__device__ __forceinline__ void split4(float4 v, uint2& h, uint2& l) {
    h.x = cvt2(v.x, v.y);
    h.y = cvt2(v.z, v.w);
    float r0 = v.x - __uint_as_float(h.x << 16);
    float r1 = v.y - __uint_as_float(h.x & 0xFFFF0000u);
    float r2 = v.z - __uint_as_float(h.y << 16);
    float r3 = v.w - __uint_as_float(h.y & 0xFFFF0000u);
    l.x = cvt2(r0, r1);
    l.y = cvt2(r2, r3);
}
__device__ __forceinline__ void cpa16(uint32_t dst, const void* src) {
    asm volatile("cp.async.cg.shared.global [%0], [%1], 16;" :: "r"(dst), "l"(src) : "memory");
}
#define CP_COMMIT() asm volatile("cp.async.commit_group;" ::: "memory")
#define CP_WAIT0()  asm volatile("cp.async.wait_group 0;" ::: "memory")

// ================= bf16-split tensor-core GEMM (R9 structure) ==============
// C[M,N] = A[M,K] * B[N,K]^T.
// EPI: 0 -> C = acc (+ add)
//      1 -> C = silu(add) * acc      (SwiGLU fused in epilogue; add = gate input h1)
#define TROW 80
#define TILE_BYTES (128 * TROW)
#define STAGE_BYTES (4 * TILE_BYTES)
#define GEMM_SMEM (2 * STAGE_BYTES)

template<int EPI>
__global__ void __launch_bounds__(256)
gemm_bf16s(const float* __restrict__ A, const float* __restrict__ B,
           float* __restrict__ C, int M, int N, int K,
           const float* __restrict__ add) {
    extern __shared__ char smem[];
    const uint32_t sbase = smem_u32(smem);

    const int tid  = threadIdx.x;
    const int warp = tid >> 5;
    const int lane = tid & 31;
    const int g = lane >> 2;
    const int t = lane & 3;
    const int blk = lane >> 3, lr = lane & 7;
    const int wm = warp >> 2;
    const int wn = warp & 3;
    const int m0 = wm * 64;
    const int n0 = wn * 32;
    const int bm = blockIdx.y * 128;
    const int bn = blockIdx.x * 128;

    // ldmatrix lane offsets
    const uint32_t aoff = (uint32_t)((blk & 1) * 8 + lr) * TROW + (uint32_t)(blk >> 1) * 16;
    const uint32_t boff = (uint32_t)((lane >> 4) * 8 + lr) * TROW + (uint32_t)(blk & 1) * 16;

    float acc[4][4][4];
    #pragma unroll
    for (int i = 0; i < 4; i++)
        #pragma unroll
        for (int j = 0; j < 4; j++)
            #pragma unroll
            for (int r = 0; r < 4; r++) acc[i][j][r] = 0.f;

    float4 va[4], vb[4];
    const int nc = K >> 5;

    // ---- prologue: load + store chunk 0
    {
        #pragma unroll
        for (int u = 0; u < 4; u++) {
            int s = tid + u * 256;
            int row = s >> 3, q = s & 7;
            va[u] = *(const float4*)(A + (size_t)(bm + row) * K + q * 4);
            vb[u] = *(const float4*)(B + (size_t)(bn + row) * K + q * 4);
        }
        char* base = smem;
        #pragma unroll
        for (int u = 0; u < 4; u++) {
            int s = tid + u * 256;
            int row = s >> 3, q = s & 7;
            uint32_t off = (uint32_t)row * TROW + (uint32_t)q * 8;
            uint2 h, l;
            split4(va[u], h, l);
            *(uint2*)(base + off)              = h;
            *(uint2*)(base + TILE_BYTES + off) = l;
            split4(vb[u], h, l);
            *(uint2*)(base + 2 * TILE_BYTES + off) = h;
            *(uint2*)(base + 3 * TILE_BYTES + off) = l;
        }
    }
    __syncthreads();

    for (int c = 0; c < nc; c++) {
        const int cur = c & 1;
        const bool more = (c + 1 < nc);

        if (more) {
            int k0 = (c + 1) << 5;
            #pragma unroll
            for (int u = 0; u < 4; u++) {
                int s = tid + u * 256;
                int row = s >> 3, q = s & 7;
                va[u] = *(const float4*)(A + (size_t)(bm + row) * K + k0 + q * 4);
                vb[u] = *(const float4*)(B + (size_t)(bn + row) * K + k0 + q * 4);
            }
        }

        // ---- compute on stage cur (ldmatrix fragments)
        {
            const uint32_t stg = sbase + (uint32_t)cur * STAGE_BYTES;

            uint32_t bh[2][2][4], bl[2][2][4];
            #pragma unroll
            for (int j2 = 0; j2 < 2; j2++)
                #pragma unroll
                for (int ks = 0; ks < 2; ks++) {
                    uint32_t ad = stg + 2 * TILE_BYTES +
                                  (uint32_t)(n0 + j2 * 16) * TROW + boff + ks * 32;
                    ldsm_x4(ad, bh[j2][ks][0], bh[j2][ks][1], bh[j2][ks][2], bh[j2][ks][3]);
                    ldsm_x4(ad + TILE_BYTES, bl[j2][ks][0], bl[j2][ks][1], bl[j2][ks][2], bl[j2][ks][3]);
                }

            #pragma unroll
            for (int i = 0; i < 4; i++) {
                uint32_t ad = stg + (uint32_t)(m0 + i * 16) * TROW + aoff;
                uint32_t ah0[4], ah1[4], al0[4], al1[4];
                ldsm_x4(ad,                     ah0[0], ah0[1], ah0[2], ah0[3]);
                ldsm_x4(ad + 32,                ah1[0], ah1[1], ah1[2], ah1[3]);
                ldsm_x4(ad + TILE_BYTES,        al0[0], al0[1], al0[2], al0[3]);
                ldsm_x4(ad + TILE_BYTES + 32,   al1[0], al1[1], al1[2], al1[3]);
                #pragma unroll
                for (int j2 = 0; j2 < 2; j2++)
                    #pragma unroll
                    for (int jj = 0; jj < 2; jj++) {
                        float* cc = acc[i][j2 * 2 + jj];
                        mma_bf16(cc, ah0, &bh[j2][0][jj * 2]);
                        mma_bf16(cc, al0, &bh[j2][0][jj * 2]);
                        mma_bf16(cc, ah0, &bl[j2][0][jj * 2]);
                        mma_bf16(cc, ah1, &bh[j2][1][jj * 2]);
                        mma_bf16(cc, al1, &bh[j2][1][jj * 2]);
                        mma_bf16(cc, ah1, &bl[j2][1][jj * 2]);
                    }
            }
        }

        if (more) {
            char* base = smem + (cur ^ 1) * STAGE_BYTES;
            #pragma unroll
            for (int u = 0; u < 4; u++) {
                int s = tid + u * 256;
                int row = s >> 3, q = s & 7;
                uint32_t off = (uint32_t)row * TROW + (uint32_t)q * 8;
                uint2 h, l;
                split4(va[u], h, l);
                *(uint2*)(base + off)              = h;
                *(uint2*)(base + TILE_BYTES + off) = l;
                split4(vb[u], h, l);
                *(uint2*)(base + 2 * TILE_BYTES + off) = h;
                *(uint2*)(base + 3 * TILE_BYTES + off) = l;
            }
        }
        __syncthreads();
    }

    // ---- epilogue
    #pragma unroll
    for (int i = 0; i < 4; i++) {
        size_t r0 = (size_t)(bm + m0 + i * 16 + g);
        size_t r1 = r0 + 8;
        #pragma unroll
        for (int j = 0; j < 4; j++) {
            int col = bn + n0 + j * 8 + t * 2;
            float2 v0 = make_float2(acc[i][j][0], acc[i][j][1]);
            float2 v1 = make_float2(acc[i][j][2], acc[i][j][3]);
            if (EPI == 1) {
                // SwiGLU: out = silu(gate) * acc ; gate = add (h1)
                float2 a0 = *(const float2*)(add + r0 * N + col);
                float2 a1 = *(const float2*)(add + r1 * N + col);
                v0.x *= a0.x / (1.f + __expf(-a0.x));
                v0.y *= a0.y / (1.f + __expf(-a0.y));
                v1.x *= a1.x / (1.f + __expf(-a1.x));
                v1.y *= a1.y / (1.f + __expf(-a1.y));
            } else if (add) {
                float2 a0 = *(const float2*)(add + r0 * N + col);
                float2 a1 = *(const float2*)(add + r1 * N + col);
                v0.x += a0.x; v0.y += a0.y;
                v1.x += a1.x; v1.y += a1.y;
            }
            *(float2*)(C + r0 * N + col) = v0;
            *(float2*)(C + r1 * N + col) = v1;
        }
    }
}

// ================= QKV pre-split: fp32 qkv -> bf16 hi/lo (Q scaled by log2e/8) =========
__global__ void __launch_bounds__(256)
split_qkv(const float* __restrict__ qkv,
          uint4* __restrict__ qh, uint4* __restrict__ ql,
          uint4* __restrict__ kh, uint4* __restrict__ kl,
          uint4* __restrict__ vh, uint4* __restrict__ vl) {
    const float qs = 1.4426950408889634f * 0.125f;
    int i = blockIdx.x * blockDim.x + threadIdx.x;
    int r  = i >> 7;
    int c8 = (i & 127) * 8;
    const float* base = qkv + (size_t)r * 3 * CC + c8;

    float4 a = *(const float4*)(base);
    float4 b = *(const float4*)(base + 4);
    a.x *= qs; a.y *= qs; a.z *= qs; a.w *= qs;
    b.x *= qs; b.y *= qs; b.z *= qs; b.w *= qs;
    uint2 h0, l0, h1, l1;
    split4(a, h0, l0); split4(b, h1, l1);
    qh[i] = make_uint4(h0.x, h0.y, h1.x, h1.y);
    ql[i] = make_uint4(l0.x, l0.y, l1.x, l1.y);

    a = *(const float4*)(base + CC);
    b = *(const float4*)(base + CC + 4);
    split4(a, h0, l0); split4(b, h1, l1);
    kh[i] = make_uint4(h0.x, h0.y, h1.x, h1.y);
    kl[i] = make_uint4(l0.x, l0.y, l1.x, l1.y);

    a = *(const float4*)(base + 2 * CC);
    b = *(const float4*)(base + 2 * CC + 4);
    split4(a, h0, l0); split4(b, h1, l1);
    vh[i] = make_uint4(h0.x, h0.y, h1.x, h1.y);
    vl[i] = make_uint4(l0.x, l0.y, l1.x, l1.y);
}

// ================= MMA flash attention (unchanged — 356-360us measured) =========
#define ASTR 144
#define QLSM (128 * ASTR)
#define ABUF0 (2 * QLSM)
#define KVT (64 * ASTR)
#define ABUFB (4 * KVT)
#define ATTN_SMEM (ABUF0 + 2 * ABUFB)  // 110592

__global__ void __launch_bounds__(256, 2)
attn_mma(const char* __restrict__ qhc, const char* __restrict__ qlc,
         const char* __restrict__ khc, const char* __restrict__ klc,
         const char* __restrict__ vhc, const char* __restrict__ vlc,
         float* __restrict__ y) {
    extern __shared__ char sm[];
    const uint32_t sb = smem_u32(sm);
    const int tid  = threadIdx.x;
    const int w    = tid >> 5;
    const int lane = tid & 31;
    const int g = lane >> 2, t = lane & 3;
    const int qt = 31 - (int)blockIdx.x;
    const int h  = blockIdx.y;
    const int q0 = qt * 128;
    const int qko = h * HD;

    const int cr = tid >> 3;
    const int ch = tid & 7;
    const size_t rowb = (size_t)2 * CC;

    #pragma unroll
    for (int u = 0; u < 8; u++) {
        int r = (u & 3) * 32 + cr;
        const char* src = ((u >> 2) ? qlc : qhc) + (size_t)(q0 + r) * rowb + qko * 2 + ch * 16;
        cpa16(sb + (u >> 2) * QLSM + (uint32_t)r * ASTR + ch * 16, src);
    }
    #pragma unroll
    for (int u = 0; u < 8; u++) {
        int r = (u & 1) * 32 + cr;
        const char* tp = (u < 2) ? khc : (u < 4) ? klc : (u < 6) ? vhc : vlc;
        const char* src = tp + (size_t)r * rowb + qko * 2 + ch * 16;
        cpa16(sb + ABUF0 + (u >> 1) * KVT + (uint32_t)r * ASTR + ch * 16, src);
    }
    CP_COMMIT();
    CP_WAIT0();
    __syncthreads();

    const int blk = lane >> 3, lr = lane & 7;
    uint32_t qfh[4][4], qfl[4][4];
    {
        uint32_t qa = sb + (uint32_t)(w * 16 + (blk & 1) * 8 + lr) * ASTR + (uint32_t)(blk >> 1) * 16;
        #pragma unroll
        for (int ks = 0; ks < 4; ks++) {
            ldsm_x4(qa + ks * 32,        qfh[ks][0], qfh[ks][1], qfh[ks][2], qfh[ks][3]);
            ldsm_x4(qa + QLSM + ks * 32, qfl[ks][0], qfl[ks][1], qfl[ks][2], qfl[ks][3]);
        }
    }

    float O[8][4];
    #pragma unroll
    for (int nf = 0; nf < 8; nf++)
        #pragma unroll
        for (int r = 0; r < 4; r++) O[nf][r] = 0.f;
    float l0 = 0.f, l1 = 0.f;

    const int nk = 2 * qt + 2;
    const int r0g = q0 + w * 16 + g;
    const uint32_t ldsmV_off = (uint32_t)((blk & 1) * 8 + lr) * ASTR + (uint32_t)(blk >> 1) * 16;
    const uint32_t ldsmK_off = (uint32_t)(((lane >> 4) << 3) | lr) * ASTR + (uint32_t)((blk & 1) * 16);

    for (int kt = 0; kt < nk; kt++) {
        const uint32_t kb = ABUF0 + (uint32_t)(kt & 1) * ABUFB;
        const bool more = (kt + 1 < nk);

        if (more) {
            int k0n = (kt + 1) * 64;
            uint32_t nb = sb + ABUF0 + (uint32_t)((kt + 1) & 1) * ABUFB;
            #pragma unroll
            for (int u = 0; u < 8; u++) {
                int r = (u & 1) * 32 + cr;
                const char* tp = (u < 2) ? khc : (u < 4) ? klc : (u < 6) ? vhc : vlc;
                const char* src = tp + (size_t)(k0n + r) * rowb + qko * 2 + ch * 16;
                cpa16(nb + (u >> 1) * KVT + (uint32_t)r * ASTR + ch * 16, src);
            }
            CP_COMMIT();
        }

        float S[8][4];
        #pragma unroll
        for (int nf = 0; nf < 8; nf++)
            #pragma unroll
            for (int r = 0; r < 4; r++) S[nf][r] = 0.f;

        {
            const uint32_t kh = sb + kb + ldsmK_off;
            #pragma unroll
            for (int ks = 0; ks < 4; ks++) {
                #pragma unroll
                for (int nfp = 0; nfp < 4; nfp++) {
                    uint32_t a = kh + (uint32_t)(nfp * 16) * ASTR + (uint32_t)(ks * 32);
                    uint32_t h0, h1, h2, h3, l0r, l1r, l2r, l3r;
                    ldsm_x4(a, h0, h1, h2, h3);
                    ldsm_x4(a + KVT, l0r, l1r, l2r, l3r);
                    uint32_t bh0[2] = {h0, h1}, bh1[2] = {h2, h3};
                    uint32_t bl0[2] = {l0r, l1r}, bl1[2] = {l2r, l3r};
                    mma_bf16(S[2 * nfp],     qfh[ks], bh0);
                    mma_bf16(S[2 * nfp],     qfl[ks], bh0);
                    mma_bf16(S[2 * nfp],     qfh[ks], bl0);
                    mma_bf16(S[2 * nfp + 1], qfh[ks], bh1);
                    mma_bf16(S[2 * nfp + 1], qfl[ks], bh1);
                    mma_bf16(S[2 * nfp + 1], qfh[ks], bl1);
                }
            }
        }

        if (kt >= 2 * qt) {
            int k0 = kt * 64;
            #pragma unroll
            for (int nf = 0; nf < 8; nf++) {
                int c = k0 + nf * 8 + 2 * t;
                if (c     > r0g)     S[nf][0] = -1e30f;
                if (c + 1 > r0g)     S[nf][1] = -1e30f;
                if (c     > r0g + 8) S[nf][2] = -1e30f;
                if (c + 1 > r0g + 8) S[nf][3] = -1e30f;
            }
        }

        #pragma unroll
        for (int nf = 0; nf < 8; nf++) {
            S[nf][0] = ex2(S[nf][0]);
            S[nf][1] = ex2(S[nf][1]);
            S[nf][2] = ex2(S[nf][2]);
            S[nf][3] = ex2(S[nf][3]);
            l0 += S[nf][0] + S[nf][1];
            l1 += S[nf][2] + S[nf][3];
        }

        {
            const uint32_t vh = sb + kb + 2 * KVT + ldsmV_off;
            #pragma unroll
            for (int ks = 0; ks < 4; ks++) {
                float p00 = S[2 * ks][0], p01 = S[2 * ks][1];
                float p02 = S[2 * ks][2], p03 = S[2 * ks][3];
                float p10 = S[2 * ks + 1][0], p11 = S[2 * ks + 1][1];
                float p12 = S[2 * ks + 1][2], p13 = S[2 * ks + 1][3];
                uint32_t pah[4], pal[4];
                pah[0] = cvt2(p00, p01);
                pah[1] = cvt2(p02, p03);
                pah[2] = cvt2(p10, p11);
                pah[3] = cvt2(p12, p13);
                pal[0] = cvt2(p00 - __uint_as_float(pah[0] << 16),
                              p01 - __uint_as_float(pah[0] & 0xFFFF0000u));
                pal[1] = cvt2(p02 - __uint_as_float(pah[1] << 16),
                              p03 - __uint_as_float(pah[1] & 0xFFFF0000u));
                pal[2] = cvt2(p10 - __uint_as_float(pah[2] << 16),
                              p11 - __uint_as_float(pah[2] & 0xFFFF0000u));
                pal[3] = cvt2(p12 - __uint_as_float(pah[3] << 16),
                              p13 - __uint_as_float(pah[3] & 0xFFFF0000u));

                uint32_t ka = vh + (uint32_t)(ks * 16) * ASTR;
                #pragma unroll
                for (int np = 0; np < 4; np++) {
                    uint32_t a = ka + (uint32_t)np * 32;
                    uint32_t b0, b1, b2, b3;
                    ldsm_x4_trans(a, b0, b1, b2, b3);
                    uint32_t bb0[2] = {b0, b1}, bb1[2] = {b2, b3};
                    mma_bf16(O[2 * np],     pah, bb0);
                    mma_bf16(O[2 * np + 1], pah, bb1);
                    mma_bf16(O[2 * np],     pal, bb0);
                    mma_bf16(O[2 * np + 1], pal, bb1);
                    ldsm_x4_trans(a + KVT, b0, b1, b2, b3);
                    uint32_t cb0[2] = {b0, b1}, cb1[2] = {b2, b3};
                    mma_bf16(O[2 * np],     pah, cb0);
                    mma_bf16(O[2 * np + 1], pah, cb1);
                }
            }
        }

        if (more) CP_WAIT0();
        __syncthreads();
    }

    l0 += __shfl_xor_sync(0xFFFFFFFFu, l0, 1);
    l0 += __shfl_xor_sync(0xFFFFFFFFu, l0, 2);
    l1 += __shfl_xor_sync(0xFFFFFFFFu, l1, 1);
    l1 += __shfl_xor_sync(0xFFFFFFFFu, l1, 2);
    float i0 = 1.f / l0, i1 = 1.f / l1;
    #pragma unroll
    for (int nf = 0; nf < 8; nf++) {
        int col = qko + nf * 8 + 2 * t;
        *(float2*)(y + (size_t)r0g * CC + col) =
            make_float2(O[nf][0] * i0, O[nf][1] * i0);
        *(float2*)(y + (size_t)(r0g + 8) * CC + col) =
            make_float2(O[nf][2] * i1, O[nf][3] * i1);
    }
}

// ---------------- RMSNorm: one block per row ----------------
__global__ void rmsnorm_kernel(const float* __restrict__ x,
                               const float* __restrict__ w,
                               float* __restrict__ o, int C) {
    int row = blockIdx.x;
    const float* xr = x + (size_t)row * C;
    float s = 0.f;
    for (int i = threadIdx.x; i < C; i += blockDim.x) {
        float v = xr[i];
        s += v * v;
    }
    __shared__ float red[32];
    #pragma unroll
    for (int off = 16; off; off >>= 1) s += __shfl_down_sync(0xFFFFFFFFu, s, off);
    if ((threadIdx.x & 31) == 0) red[threadIdx.x >> 5] = s;
    __syncthreads();
    if (threadIdx.x < 32) {
        float v = (threadIdx.x < (blockDim.x >> 5)) ? red[threadIdx.x] : 0.f;
        #pragma unroll
        for (int off = 16; off; off >>= 1) v += __shfl_down_sync(0xFFFFFFFFu, v, off);
        if (threadIdx.x == 0) red[0] = v;
    }
    __syncthreads();
    float inv = rsqrtf(red[0] / (float)C + 1e-6f);
    for (int i = threadIdx.x; i < C; i += blockDim.x)
        o[(size_t)row * C + i] = xr[i] * inv * w[i];
}

// ---------------- launch ----------------
extern "C" void kernel_launch(void* const* d_in, const int* in_sizes, int n_in,
                              void* d_out, int out_size) {
    const float* x           = (const float*)d_in[0];
    const float* attn_norm_w = (const float*)d_in[1];
    const float* ffn_norm_w  = (const float*)d_in[2];
    const float* c_attn_w    = (const float*)d_in[3];
    const float* c_proj_w    = (const float*)d_in[4];
    const float* w1          = (const float*)d_in[5];
    const float* w2          = (const float*)d_in[6];
    const float* w3          = (const float*)d_in[7];
    float* out = (float*)d_out;

    float *xn, *qkv, *yb, *x1, *h1;
    cudaGetSymbolAddress((void**)&xn,  g_xn);
    cudaGetSymbolAddress((void**)&qkv, g_qkv);
    cudaGetSymbolAddress((void**)&yb,  g_y);
    cudaGetSymbolAddress((void**)&x1,  g_x1);
    cudaGetSymbolAddress((void**)&h1,  g_h1);
    void *qh, *ql, *kh, *kl, *vh, *vl;
    cudaGetSymbolAddress(&qh, g_qh);
    cudaGetSymbolAddress(&ql, g_ql);
    cudaGetSymbolAddress(&kh, g_kh);
    cudaGetSymbolAddress(&kl, g_kl);
    cudaGetSymbolAddress(&vh, g_vh);
    cudaGetSymbolAddress(&vl, g_vl);

    cudaFuncSetAttribute(gemm_bf16s<0>, cudaFuncAttributeMaxDynamicSharedMemorySize, GEMM_SMEM);
    cudaFuncSetAttribute(gemm_bf16s<1>, cudaFuncAttributeMaxDynamicSharedMemorySize, GEMM_SMEM);
    cudaFuncSetAttribute(attn_mma, cudaFuncAttributeMaxDynamicSharedMemorySize, ATTN_SMEM);

    // 1) xn = rmsnorm(x, attn_norm_w)
    rmsnorm_kernel<<<TT, 256>>>(x, attn_norm_w, xn, CC);

    // 2) qkv = xn @ c_attn_w^T       [4096, 3072]
    gemm_bf16s<0><<<dim3(3 * CC / 128, TT / 128), 256, GEMM_SMEM>>>(
        xn, c_attn_w, qkv, TT, 3 * CC, CC, nullptr);

    // 3) pre-split qkv into bf16 hi/lo tensors (Q pre-scaled)
    split_qkv<<<TT * CC / 8 / 256, 256>>>(qkv, (uint4*)qh, (uint4*)ql,
                                          (uint4*)kh, (uint4*)kl, (uint4*)vh, (uint4*)vl);

    // 4) y = causal_attention       [4096, 1024]
    attn_mma<<<dim3(TT / 128, NH), 256, ATTN_SMEM>>>(
        (const char*)qh, (const char*)ql, (const char*)kh,
        (const char*)kl, (const char*)vh, (const char*)vl, yb);

    // 5) x1 = y @ c_proj_w^T + x
    gemm_bf16s<0><<<dim3(CC / 128, TT / 128), 256, GEMM_SMEM>>>(
        yb, c_proj_w, x1, TT, CC, CC, x);

    // 6) xn = rmsnorm(x1, ffn_norm_w)
    rmsnorm_kernel<<<TT, 256>>>(x1, ffn_norm_w, xn, CC);

    // 7) h1 = xn @ w1^T
    gemm_bf16s<0><<<dim3(HF / 128, TT / 128), 256, GEMM_SMEM>>>(
        xn, w1, h1, TT, HF, CC, nullptr);

    // 8) h1 = silu(h1) * (xn @ w3^T)   (SwiGLU fused into h3-GEMM epilogue)
    gemm_bf16s<1><<<dim3(HF / 128, TT / 128), 256, GEMM_SMEM>>>(
        xn, w3, h1, TT, HF, CC, h1);

    // 9) out = h1 @ w2^T + x1
    gemm_bf16s<0><<<dim3(CC / 128, TT / 128), 256, GEMM_SMEM>>>(
        h1, w2, out, TT, CC, HF, x1);
}

// round 14
// speedup vs baseline: 2.0756x; 1.0834x over previous
#include <cuda_runtime.h>
#include <cuda_bf16.h>
#include <cstdint>
#include <math.h>

// Problem dims (fixed by the reference)
#define TT 4096
#define CC 1024
#define HF 4096
#define NH 16
#define HD 64

// ---------------- scratch (device globals: allocation-free) ----------------
__device__ float g_xn [(size_t)TT * CC];
__device__ float g_qkv[(size_t)TT * 3 * CC];
__device__ float g_y  [(size_t)TT * CC];
__device__ float g_x1 [(size_t)TT * CC];
__device__ float g_h1 [(size_t)TT * HF];
__device__ float g_h3 [(size_t)TT * HF];
// pre-split bf16 Q/K/V for attention (hi + lo residual), Q pre-scaled by log2e/8.
__device__ uint4 g_qh[(size_t)TT * CC / 8];
__device__ uint4 g_ql[(size_t)TT * CC / 8];
__device__ uint4 g_kh[(size_t)TT * CC / 8];
__device__ uint4 g_kl[(size_t)TT * CC / 8];
__device__ uint4 g_vh[(size_t)TT * CC / 8];
__device__ uint4 g_vl[(size_t)TT * CC / 8];
// pre-split bf16 GEMM operands
#define NWELEM 16777216ull          // c_attn 3M | c_proj 1M | w1 4M | w3 4M | w2 4M
#define OFF_CATTN 0ull
#define OFF_CPROJ 3145728ull
#define OFF_W1    4194304ull
#define OFF_W3    8388608ull
#define OFF_W2    12582912ull
__device__ uint2 g_wh[NWELEM / 4];  // weight hi
__device__ uint2 g_wl[NWELEM / 4];  // weight lo
__device__ uint2 g_axh[(size_t)TT * CC / 4];   // activation hi (xn / y, reused)
__device__ uint2 g_axl[(size_t)TT * CC / 4];
__device__ uint2 g_hh[(size_t)TT * HF / 4];    // h = silu(h1)*h3 hi
__device__ uint2 g_hl[(size_t)TT * HF / 4];

// ================= helpers =================
__device__ __forceinline__ uint32_t smem_u32(const void* p) {
    uint32_t a;
    asm("{ .reg .u64 t; cvta.to.shared.u64 t, %1; cvt.u32.u64 %0, t; }" : "=r"(a) : "l"(p));
    return a;
}
__device__ __forceinline__ uint32_t cvt2(float a, float b) {
    uint32_t r;
    asm("cvt.rn.satfinite.bf16x2.f32 %0, %1, %2;" : "=r"(r) : "f"(b), "f"(a));
    return r;
}
__device__ __forceinline__ float ex2(float x) {
    float r;
    asm("ex2.approx.f32 %0, %1;" : "=f"(r) : "f"(x));
    return r;
}
__device__ __forceinline__ void mma_bf16(float* c, const uint32_t* a, const uint32_t* b) {
    asm volatile(
        "mma.sync.aligned.m16n8k16.row.col.f32.bf16.bf16.f32 "
        "{%0,%1,%2,%3}, {%4,%5,%6,%7}, {%8,%9}, {%0,%1,%2,%3};"
        : "+f"(c[0]), "+f"(c[1]), "+f"(c[2]), "+f"(c[3])
        : "r"(a[0]), "r"(a[1]), "r"(a[2]), "r"(a[3]), "r"(b[0]), "r"(b[1]));
}
__device__ __forceinline__ void ldsm_x4(uint32_t addr, uint32_t& b0, uint32_t& b1,
                                        uint32_t& b2, uint32_t& b3) {
    asm volatile("ldmatrix.sync.aligned.m8n8.x4.shared.b16 {%0,%1,%2,%3}, [%4];"
                 : "=r"(b0), "=r"(b1), "=r"(b2), "=r"(b3) : "r"(addr));
}
__device__ __forceinline__ void ldsm_x4_trans(uint32_t addr, uint32_t& b0, uint32_t& b1,
                                              uint32_t& b2, uint32_t& b3) {
    asm volatile("ldmatrix.sync.aligned.m8n8.x4.trans.shared.b16 {%0,%1,%2,%3}, [%4];"
                 : "=r"(b0), "=r"(b1), "=r"(b2), "=r"(b3) : "r"(addr));
}
__device__ __forceinline__ void split4(float4 v, uint2& h, uint2& l) {
    h.x = cvt2(v.x, v.y);
    h.y = cvt2(v.z, v.w);
    float r0 = v.x - __uint_as_float(h.x << 16);
    float r1 = v.y - __uint_as_float(h.x & 0xFFFF0000u);
    float r2 = v.z - __uint_as_float(h.y << 16);
    float r3 = v.w - __uint_as_float(h.y & 0xFFFF0000u);
    l.x = cvt2(r0, r1);
    l.y = cvt2(r2, r3);
}
__device__ __forceinline__ void cpa16(uint32_t dst, const void* src) {
    asm volatile("cp.async.cg.shared.global [%0], [%1], 16;" :: "r"(dst), "l"(src) : "memory");
}
#define CP_COMMIT() asm volatile("cp.async.commit_group;" ::: "memory")
#define CP_WAIT0()  asm volatile("cp.async.wait_group 0;" ::: "memory")

// ================= pre-split bf16 GEMM: pure cp.async data path ==============
// C[M,N] = A[M,K] * B[N,K]^T (+ add). Operands already bf16 hi/lo in gmem,
// row-major [rows][K] bf16. 128x128x32 CTA tile, 256 thr, warp tile 64x32.
#define TROW 80
#define TILE_BYTES (128 * TROW)
#define STAGE_BYTES (4 * TILE_BYTES)     // Ah, Al, Bh, Bl
#define GEMM_SMEM (2 * STAGE_BYTES)      // 81920

__global__ void __launch_bounds__(256)
gemm_pre(const char* __restrict__ Ah, const char* __restrict__ Al,
         const char* __restrict__ Bh, const char* __restrict__ Bl,
         float* __restrict__ C, int M, int N, int K,
         const float* __restrict__ add) {
    extern __shared__ char smem[];
    const uint32_t sbase = smem_u32(smem);

    const int tid  = threadIdx.x;
    const int warp = tid >> 5;
    const int lane = tid & 31;
    const int g = lane >> 2;
    const int t = lane & 3;
    const int blk = lane >> 3, lr = lane & 7;
    const int wm = warp >> 2;
    const int wn = warp & 3;
    const int m0 = wm * 64;
    const int n0 = wn * 32;
    const int bm = blockIdx.y * 128;
    const int bn = blockIdx.x * 128;
    const size_t K2 = (size_t)K * 2;     // row bytes in split arrays

    const uint32_t aoff = (uint32_t)((blk & 1) * 8 + lr) * TROW + (uint32_t)(blk >> 1) * 16;
    const uint32_t boff = (uint32_t)((lane >> 4) * 8 + lr) * TROW + (uint32_t)(blk & 1) * 16;

    float acc[4][4][4];
    #pragma unroll
    for (int i = 0; i < 4; i++)
        #pragma unroll
        for (int j = 0; j < 4; j++)
            #pragma unroll
            for (int r = 0; r < 4; r++) acc[i][j][r] = 0.f;

    const int nc = K >> 5;

    // cp.async chunk c (64 bytes per row) into stage st
    auto issue = [&](int c, int st) {
        const uint32_t stg = sbase + (uint32_t)st * STAGE_BYTES;
        const uint32_t cb = (uint32_t)c << 6;
        #pragma unroll
        for (int u = 0; u < 8; u++) {
            int id  = tid + u * 256;      // 0..2047
            int ten = id >> 9;            // 0:Ah 1:Al 2:Bh 3:Bl
            int wc  = id & 511;
            int row = wc >> 2, c4 = (wc & 3) * 16;
            const char* base = (ten == 0) ? Ah : (ten == 1) ? Al : (ten == 2) ? Bh : Bl;
            int grow = (ten < 2) ? (bm + row) : (bn + row);
            cpa16(stg + (uint32_t)ten * TILE_BYTES + (uint32_t)row * TROW + c4,
                  base + (size_t)grow * K2 + cb + c4);
        }
        CP_COMMIT();
    };

    // ---- prologue
    issue(0, 0);
    CP_WAIT0();
    __syncthreads();
    if (nc > 1) issue(1, 1);

    for (int c = 0; c < nc; c++) {
        const int cur = c & 1;

        // ---- compute on stage cur (overlaps cp.async of chunk c+1)
        {
            const uint32_t stg = sbase + (uint32_t)cur * STAGE_BYTES;

            uint32_t bh[2][2][4], bl[2][2][4];
            #pragma unroll
            for (int j2 = 0; j2 < 2; j2++)
                #pragma unroll
                for (int ks = 0; ks < 2; ks++) {
                    uint32_t ad = stg + 2 * TILE_BYTES +
                                  (uint32_t)(n0 + j2 * 16) * TROW + boff + ks * 32;
                    ldsm_x4(ad, bh[j2][ks][0], bh[j2][ks][1], bh[j2][ks][2], bh[j2][ks][3]);
                    ldsm_x4(ad + TILE_BYTES, bl[j2][ks][0], bl[j2][ks][1], bl[j2][ks][2], bl[j2][ks][3]);
                }

            #pragma unroll
            for (int i = 0; i < 4; i++) {
                uint32_t ad = stg + (uint32_t)(m0 + i * 16) * TROW + aoff;
                uint32_t ah0[4], ah1[4], al0[4], al1[4];
                ldsm_x4(ad,                     ah0[0], ah0[1], ah0[2], ah0[3]);
                ldsm_x4(ad + 32,                ah1[0], ah1[1], ah1[2], ah1[3]);
                ldsm_x4(ad + TILE_BYTES,        al0[0], al0[1], al0[2], al0[3]);
                ldsm_x4(ad + TILE_BYTES + 32,   al1[0], al1[1], al1[2], al1[3]);
                #pragma unroll
                for (int j2 = 0; j2 < 2; j2++)
                    #pragma unroll
                    for (int jj = 0; jj < 2; jj++) {
                        float* cc = acc[i][j2 * 2 + jj];
                        mma_bf16(cc, ah0, &bh[j2][0][jj * 2]);
                        mma_bf16(cc, al0, &bh[j2][0][jj * 2]);
                        mma_bf16(cc, ah0, &bl[j2][0][jj * 2]);
                        mma_bf16(cc, ah1, &bh[j2][1][jj * 2]);
                        mma_bf16(cc, al1, &bh[j2][1][jj * 2]);
                        mma_bf16(cc, ah1, &bl[j2][1][jj * 2]);
                    }
            }
        }

        if (c + 1 < nc) {
            CP_WAIT0();            // chunk c+1 landed in the other stage
            __syncthreads();       // all warps done reading stage cur
            if (c + 2 < nc) issue(c + 2, cur);   // refill freed stage
        }
    }

    // ---- epilogue
    #pragma unroll
    for (int i = 0; i < 4; i++) {
        size_t r0 = (size_t)(bm + m0 + i * 16 + g);
        size_t r1 = r0 + 8;
        #pragma unroll
        for (int j = 0; j < 4; j++) {
            int col = bn + n0 + j * 8 + t * 2;
            float2 v0 = make_float2(acc[i][j][0], acc[i][j][1]);
            float2 v1 = make_float2(acc[i][j][2], acc[i][j][3]);
            if (add) {
                float2 a0 = *(const float2*)(add + r0 * N + col);
                float2 a1 = *(const float2*)(add + r1 * N + col);
                v0.x += a0.x; v0.y += a0.y;
                v1.x += a1.x; v1.y += a1.y;
            }
            *(float2*)(C + r0 * N + col) = v0;
            *(float2*)(C + r1 * N + col) = v1;
        }
    }
}

// ================= generic fp32 -> bf16 hi/lo split ==============
__global__ void __launch_bounds__(256)
split_f32(const float4* __restrict__ src, uint2* __restrict__ hi,
          uint2* __restrict__ lo, int n4) {
    int i = blockIdx.x * blockDim.x + threadIdx.x;
    if (i < n4) {
        uint2 h, l;
        split4(src[i], h, l);
        hi[i] = h;
        lo[i] = l;
    }
}

// ================= SwiGLU with split output: h = silu(h1)*h3 -> bf16 hi/lo ======
__global__ void __launch_bounds__(256)
swiglu_split(const float4* __restrict__ h1, const float4* __restrict__ h3,
             uint2* __restrict__ hh, uint2* __restrict__ hl, int n4) {
    int i = blockIdx.x * blockDim.x + threadIdx.x;
    if (i < n4) {
        float4 a = h1[i];
        float4 b = h3[i];
        a.x = a.x / (1.f + __expf(-a.x)) * b.x;
        a.y = a.y / (1.f + __expf(-a.y)) * b.y;
        a.z = a.z / (1.f + __expf(-a.z)) * b.z;
        a.w = a.w / (1.f + __expf(-a.w)) * b.w;
        uint2 h, l;
        split4(a, h, l);
        hh[i] = h;
        hl[i] = l;
    }
}

// ================= QKV pre-split: fp32 qkv -> bf16 hi/lo (Q scaled) =========
__global__ void __launch_bounds__(256)
split_qkv(const float* __restrict__ qkv,
          uint4* __restrict__ qh, uint4* __restrict__ ql,
          uint4* __restrict__ kh, uint4* __restrict__ kl,
          uint4* __restrict__ vh, uint4* __restrict__ vl) {
    const float qs = 1.4426950408889634f * 0.125f;
    int i = blockIdx.x * blockDim.x + threadIdx.x;
    int r  = i >> 7;
    int c8 = (i & 127) * 8;
    const float* base = qkv + (size_t)r * 3 * CC + c8;

    float4 a = *(const float4*)(base);
    float4 b = *(const float4*)(base + 4);
    a.x *= qs; a.y *= qs; a.z *= qs; a.w *= qs;
    b.x *= qs; b.y *= qs; b.z *= qs; b.w *= qs;
    uint2 h0, l0, h1, l1;
    split4(a, h0, l0); split4(b, h1, l1);
    qh[i] = make_uint4(h0.x, h0.y, h1.x, h1.y);
    ql[i] = make_uint4(l0.x, l0.y, l1.x, l1.y);

    a = *(const float4*)(base + CC);
    b = *(const float4*)(base + CC + 4);
    split4(a, h0, l0); split4(b, h1, l1);
    kh[i] = make_uint4(h0.x, h0.y, h1.x, h1.y);
    kl[i] = make_uint4(l0.x, l0.y, l1.x, l1.y);

    a = *(const float4*)(base + 2 * CC);
    b = *(const float4*)(base + 2 * CC + 4);
    split4(a, h0, l0); split4(b, h1, l1);
    vh[i] = make_uint4(h0.x, h0.y, h1.x, h1.y);
    vl[i] = make_uint4(l0.x, l0.y, l1.x, l1.y);
}

// ================= MMA flash attention (unchanged — 356-360us measured) =========
#define ASTR 144
#define QLSM (128 * ASTR)
#define ABUF0 (2 * QLSM)
#define KVT (64 * ASTR)
#define ABUFB (4 * KVT)
#define ATTN_SMEM (ABUF0 + 2 * ABUFB)  // 110592

__global__ void __launch_bounds__(256, 2)
attn_mma(const char* __restrict__ qhc, const char* __restrict__ qlc,
         const char* __restrict__ khc, const char* __restrict__ klc,
         const char* __restrict__ vhc, const char* __restrict__ vlc,
         float* __restrict__ y) {
    extern __shared__ char sm[];
    const uint32_t sb = smem_u32(sm);
    const int tid  = threadIdx.x;
    const int w    = tid >> 5;
    const int lane = tid & 31;
    const int g = lane >> 2, t = lane & 3;
    const int qt = 31 - (int)blockIdx.x;
    const int h  = blockIdx.y;
    const int q0 = qt * 128;
    const int qko = h * HD;

    const int cr = tid >> 3;
    const int ch = tid & 7;
    const size_t rowb = (size_t)2 * CC;

    #pragma unroll
    for (int u = 0; u < 8; u++) {
        int r = (u & 3) * 32 + cr;
        const char* src = ((u >> 2) ? qlc : qhc) + (size_t)(q0 + r) * rowb + qko * 2 + ch * 16;
        cpa16(sb + (u >> 2) * QLSM + (uint32_t)r * ASTR + ch * 16, src);
    }
    #pragma unroll
    for (int u = 0; u < 8; u++) {
        int r = (u & 1) * 32 + cr;
        const char* tp = (u < 2) ? khc : (u < 4) ? klc : (u < 6) ? vhc : vlc;
        const char* src = tp + (size_t)r * rowb + qko * 2 + ch * 16;
        cpa16(sb + ABUF0 + (u >> 1) * KVT + (uint32_t)r * ASTR + ch * 16, src);
    }
    CP_COMMIT();
    CP_WAIT0();
    __syncthreads();

    const int blk = lane >> 3, lr = lane & 7;
    uint32_t qfh[4][4], qfl[4][4];
    {
        uint32_t qa = sb + (uint32_t)(w * 16 + (blk & 1) * 8 + lr) * ASTR + (uint32_t)(blk >> 1) * 16;
        #pragma unroll
        for (int ks = 0; ks < 4; ks++) {
            ldsm_x4(qa + ks * 32,        qfh[ks][0], qfh[ks][1], qfh[ks][2], qfh[ks][3]);
            ldsm_x4(qa + QLSM + ks * 32, qfl[ks][0], qfl[ks][1], qfl[ks][2], qfl[ks][3]);
        }
    }

    float O[8][4];
    #pragma unroll
    for (int nf = 0; nf < 8; nf++)
        #pragma unroll
        for (int r = 0; r < 4; r++) O[nf][r] = 0.f;
    float l0 = 0.f, l1 = 0.f;

    const int nk = 2 * qt + 2;
    const int r0g = q0 + w * 16 + g;
    const uint32_t ldsmV_off = (uint32_t)((blk & 1) * 8 + lr) * ASTR + (uint32_t)(blk >> 1) * 16;
    const uint32_t ldsmK_off = (uint32_t)(((lane >> 4) << 3) | lr) * ASTR + (uint32_t)((blk & 1) * 16);

    for (int kt = 0; kt < nk; kt++) {
        const uint32_t kb = ABUF0 + (uint32_t)(kt & 1) * ABUFB;
        const bool more = (kt + 1 < nk);

        if (more) {
            int k0n = (kt + 1) * 64;
            uint32_t nb = sb + ABUF0 + (uint32_t)((kt + 1) & 1) * ABUFB;
            #pragma unroll
            for (int u = 0; u < 8; u++) {
                int r = (u & 1) * 32 + cr;
                const char* tp = (u < 2) ? khc : (u < 4) ? klc : (u < 6) ? vhc : vlc;
                const char* src = tp + (size_t)(k0n + r) * rowb + qko * 2 + ch * 16;
                cpa16(nb + (u >> 1) * KVT + (uint32_t)r * ASTR + ch * 16, src);
            }
            CP_COMMIT();
        }

        float S[8][4];
        #pragma unroll
        for (int nf = 0; nf < 8; nf++)
            #pragma unroll
            for (int r = 0; r < 4; r++) S[nf][r] = 0.f;

        {
            const uint32_t kh = sb + kb + ldsmK_off;
            #pragma unroll
            for (int ks = 0; ks < 4; ks++) {
                #pragma unroll
                for (int nfp = 0; nfp < 4; nfp++) {
                    uint32_t a = kh + (uint32_t)(nfp * 16) * ASTR + (uint32_t)(ks * 32);
                    uint32_t h0, h1, h2, h3, l0r, l1r, l2r, l3r;
                    ldsm_x4(a, h0, h1, h2, h3);
                    ldsm_x4(a + KVT, l0r, l1r, l2r, l3r);
                    uint32_t bh0[2] = {h0, h1}, bh1[2] = {h2, h3};
                    uint32_t bl0[2] = {l0r, l1r}, bl1[2] = {l2r, l3r};
                    mma_bf16(S[2 * nfp],     qfh[ks], bh0);
                    mma_bf16(S[2 * nfp],     qfl[ks], bh0);
                    mma_bf16(S[2 * nfp],     qfh[ks], bl0);
                    mma_bf16(S[2 * nfp + 1], qfh[ks], bh1);
                    mma_bf16(S[2 * nfp + 1], qfl[ks], bh1);
                    mma_bf16(S[2 * nfp + 1], qfh[ks], bl1);
                }
            }
        }

        if (kt >= 2 * qt) {
            int k0 = kt * 64;
            #pragma unroll
            for (int nf = 0; nf < 8; nf++) {
                int c = k0 + nf * 8 + 2 * t;
                if (c     > r0g)     S[nf][0] = -1e30f;
                if (c + 1 > r0g)     S[nf][1] = -1e30f;
                if (c     > r0g + 8) S[nf][2] = -1e30f;
                if (c + 1 > r0g + 8) S[nf][3] = -1e30f;
            }
        }

        #pragma unroll
        for (int nf = 0; nf < 8; nf++) {
            S[nf][0] = ex2(S[nf][0]);
            S[nf][1] = ex2(S[nf][1]);
            S[nf][2] = ex2(S[nf][2]);
            S[nf][3] = ex2(S[nf][3]);
            l0 += S[nf][0] + S[nf][1];
            l1 += S[nf][2] + S[nf][3];
        }

        {
            const uint32_t vh = sb + kb + 2 * KVT + ldsmV_off;
            #pragma unroll
            for (int ks = 0; ks < 4; ks++) {
                float p00 = S[2 * ks][0], p01 = S[2 * ks][1];
                float p02 = S[2 * ks][2], p03 = S[2 * ks][3];
                float p10 = S[2 * ks + 1][0], p11 = S[2 * ks + 1][1];
                float p12 = S[2 * ks + 1][2], p13 = S[2 * ks + 1][3];
                uint32_t pah[4], pal[4];
                pah[0] = cvt2(p00, p01);
                pah[1] = cvt2(p02, p03);
                pah[2] = cvt2(p10, p11);
                pah[3] = cvt2(p12, p13);
                pal[0] = cvt2(p00 - __uint_as_float(pah[0] << 16),
                              p01 - __uint_as_float(pah[0] & 0xFFFF0000u));
                pal[1] = cvt2(p02 - __uint_as_float(pah[1] << 16),
                              p03 - __uint_as_float(pah[1] & 0xFFFF0000u));
                pal[2] = cvt2(p10 - __uint_as_float(pah[2] << 16),
                              p11 - __uint_as_float(pah[2] & 0xFFFF0000u));
                pal[3] = cvt2(p12 - __uint_as_float(pah[3] << 16),
                              p13 - __uint_as_float(pah[3] & 0xFFFF0000u));

                uint32_t ka = vh + (uint32_t)(ks * 16) * ASTR;
                #pragma unroll
                for (int np = 0; np < 4; np++) {
                    uint32_t a = ka + (uint32_t)np * 32;
                    uint32_t b0, b1, b2, b3;
                    ldsm_x4_trans(a, b0, b1, b2, b3);
                    uint32_t bb0[2] = {b0, b1}, bb1[2] = {b2, b3};
                    mma_bf16(O[2 * np],     pah, bb0);
                    mma_bf16(O[2 * np + 1], pah, bb1);
                    mma_bf16(O[2 * np],     pal, bb0);
                    mma_bf16(O[2 * np + 1], pal, bb1);
                    ldsm_x4_trans(a + KVT, b0, b1, b2, b3);
                    uint32_t cb0[2] = {b0, b1}, cb1[2] = {b2, b3};
                    mma_bf16(O[2 * np],     pah, cb0);
                    mma_bf16(O[2 * np + 1], pah, cb1);
                }
            }
        }

        if (more) CP_WAIT0();
        __syncthreads();
    }

    l0 += __shfl_xor_sync(0xFFFFFFFFu, l0, 1);
    l0 += __shfl_xor_sync(0xFFFFFFFFu, l0, 2);
    l1 += __shfl_xor_sync(0xFFFFFFFFu, l1, 1);
    l1 += __shfl_xor_sync(0xFFFFFFFFu, l1, 2);
    float i0 = 1.f / l0, i1 = 1.f / l1;
    #pragma unroll
    for (int nf = 0; nf < 8; nf++) {
        int col = qko + nf * 8 + 2 * t;
        *(float2*)(y + (size_t)r0g * CC + col) =
            make_float2(O[nf][0] * i0, O[nf][1] * i0);
        *(float2*)(y + (size_t)(r0g + 8) * CC + col) =
            make_float2(O[nf][2] * i1, O[nf][3] * i1);
    }
}

// ---------------- RMSNorm: one block per row ----------------
__global__ void rmsnorm_kernel(const float* __restrict__ x,
                               const float* __restrict__ w,
                               float* __restrict__ o, int C) {
    int row = blockIdx.x;
    const float* xr = x + (size_t)row * C;
    float s = 0.f;
    for (int i = threadIdx.x; i < C; i += blockDim.x) {
        float v = xr[i];
        s += v * v;
    }
    __shared__ float red[32];
    #pragma unroll
    for (int off = 16; off; off >>= 1) s += __shfl_down_sync(0xFFFFFFFFu, s, off);
    if ((threadIdx.x & 31) == 0) red[threadIdx.x >> 5] = s;
    __syncthreads();
    if (threadIdx.x < 32) {
        float v = (threadIdx.x < (blockDim.x >> 5)) ? red[threadIdx.x] : 0.f;
        #pragma unroll
        for (int off = 16; off; off >>= 1) v += __shfl_down_sync(0xFFFFFFFFu, v, off);
        if (threadIdx.x == 0) red[0] = v;
    }
    __syncthreads();
    float inv = rsqrtf(red[0] / (float)C + 1e-6f);
    for (int i = threadIdx.x; i < C; i += blockDim.x)
        o[(size_t)row * C + i] = xr[i] * inv * w[i];
}

// ---------------- launch ----------------
extern "C" void kernel_launch(void* const* d_in, const int* in_sizes, int n_in,
                              void* d_out, int out_size) {
    const float* x           = (const float*)d_in[0];
    const float* attn_norm_w = (const float*)d_in[1];
    const float* ffn_norm_w  = (const float*)d_in[2];
    const float* c_attn_w    = (const float*)d_in[3];
    const float* c_proj_w    = (const float*)d_in[4];
    const float* w1          = (const float*)d_in[5];
    const float* w2          = (const float*)d_in[6];
    const float* w3          = (const float*)d_in[7];
    float* out = (float*)d_out;

    float *xn, *qkv, *yb, *x1, *h1, *h3;
    cudaGetSymbolAddress((void**)&xn,  g_xn);
    cudaGetSymbolAddress((void**)&qkv, g_qkv);
    cudaGetSymbolAddress((void**)&yb,  g_y);
    cudaGetSymbolAddress((void**)&x1,  g_x1);
    cudaGetSymbolAddress((void**)&h1,  g_h1);
    cudaGetSymbolAddress((void**)&h3,  g_h3);
    void *qh, *ql, *kh, *kl, *vh, *vl, *whv, *wlv, *axh, *axl, *hh, *hl;
    cudaGetSymbolAddress(&qh, g_qh);
    cudaGetSymbolAddress(&ql, g_ql);
    cudaGetSymbolAddress(&kh, g_kh);
    cudaGetSymbolAddress(&kl, g_kl);
    cudaGetSymbolAddress(&vh, g_vh);
    cudaGetSymbolAddress(&vl, g_vl);
    cudaGetSymbolAddress(&whv, g_wh);
    cudaGetSymbolAddress(&wlv, g_wl);
    cudaGetSymbolAddress(&axh, g_axh);
    cudaGetSymbolAddress(&axl, g_axl);
    cudaGetSymbolAddress(&hh, g_hh);
    cudaGetSymbolAddress(&hl, g_hl);

    const char* whc = (const char*)whv;
    const char* wlc = (const char*)wlv;
    uint2* whu = (uint2*)whv;
    uint2* wlu = (uint2*)wlv;

    cudaFuncSetAttribute(gemm_pre, cudaFuncAttributeMaxDynamicSharedMemorySize, GEMM_SMEM);
    cudaFuncSetAttribute(attn_mma, cudaFuncAttributeMaxDynamicSharedMemorySize, ATTN_SMEM);

    // 0) split weights into bf16 hi/lo
    split_f32<<<(3 * CC * CC / 4) / 256, 256>>>((const float4*)c_attn_w,
        whu + OFF_CATTN / 4, wlu + OFF_CATTN / 4, 3 * CC * CC / 4);
    split_f32<<<(CC * CC / 4) / 256, 256>>>((const float4*)c_proj_w,
        whu + OFF_CPROJ / 4, wlu + OFF_CPROJ / 4, CC * CC / 4);
    split_f32<<<(HF * CC / 4) / 256, 256>>>((const float4*)w1,
        whu + OFF_W1 / 4, wlu + OFF_W1 / 4, HF * CC / 4);
    split_f32<<<(HF * CC / 4) / 256, 256>>>((const float4*)w3,
        whu + OFF_W3 / 4, wlu + OFF_W3 / 4, HF * CC / 4);
    split_f32<<<(CC * HF / 4) / 256, 256>>>((const float4*)w2,
        whu + OFF_W2 / 4, wlu + OFF_W2 / 4, CC * HF / 4);

    // 1) xn = rmsnorm(x, attn_norm_w); split
    rmsnorm_kernel<<<TT, 256>>>(x, attn_norm_w, xn, CC);
    split_f32<<<(TT * CC / 4) / 256, 256>>>((const float4*)xn, (uint2*)axh, (uint2*)axl, TT * CC / 4);

    // 2) qkv = xn @ c_attn_w^T
    gemm_pre<<<dim3(3 * CC / 128, TT / 128), 256, GEMM_SMEM>>>(
        (const char*)axh, (const char*)axl,
        whc + OFF_CATTN * 2, wlc + OFF_CATTN * 2, qkv, TT, 3 * CC, CC, nullptr);

    // 3) pre-split qkv for attention (Q pre-scaled)
    split_qkv<<<TT * CC / 8 / 256, 256>>>(qkv, (uint4*)qh, (uint4*)ql,
                                          (uint4*)kh, (uint4*)kl, (uint4*)vh, (uint4*)vl);

    // 4) y = causal_attention
    attn_mma<<<dim3(TT / 128, NH), 256, ATTN_SMEM>>>(
        (const char*)qh, (const char*)ql, (const char*)kh,
        (const char*)kl, (const char*)vh, (const char*)vl, yb);

    // 5) x1 = y @ c_proj_w^T + x
    split_f32<<<(TT * CC / 4) / 256, 256>>>((const float4*)yb, (uint2*)axh, (uint2*)axl, TT * CC / 4);
    gemm_pre<<<dim3(CC / 128, TT / 128), 256, GEMM_SMEM>>>(
        (const char*)axh, (const char*)axl,
        whc + OFF_CPROJ * 2, wlc + OFF_CPROJ * 2, x1, TT, CC, CC, x);

    // 6) xn = rmsnorm(x1, ffn_norm_w); split
    rmsnorm_kernel<<<TT, 256>>>(x1, ffn_norm_w, xn, CC);
    split_f32<<<(TT * CC / 4) / 256, 256>>>((const float4*)xn, (uint2*)axh, (uint2*)axl, TT * CC / 4);

    // 7) h1 = xn @ w1^T ; h3 = xn @ w3^T
    gemm_pre<<<dim3(HF / 128, TT / 128), 256, GEMM_SMEM>>>(
        (const char*)axh, (const char*)axl,
        whc + OFF_W1 * 2, wlc + OFF_W1 * 2, h1, TT, HF, CC, nullptr);
    gemm_pre<<<dim3(HF / 128, TT / 128), 256, GEMM_SMEM>>>(
        (const char*)axh, (const char*)axl,
        whc + OFF_W3 * 2, wlc + OFF_W3 * 2, h3, TT, HF, CC, nullptr);

    // 8) h = silu(h1) * h3, split output
    swiglu_split<<<(TT * HF / 4) / 256, 256>>>((const float4*)h1, (const float4*)h3,
                                               (uint2*)hh, (uint2*)hl, TT * HF / 4);

    // 9) out = h @ w2^T + x1
    gemm_pre<<<dim3(CC / 128, TT / 128), 256, GEMM_SMEM>>>(
        (const char*)hh, (const char*)hl,
        whc + OFF_W2 * 2, wlc + OFF_W2 * 2, out, TT, CC, HF, x1);
}

// round 15
// speedup vs baseline: 2.1020x; 1.0127x over previous
#include <cuda_runtime.h>
#include <cuda_bf16.h>
#include <cstdint>
#include <math.h>

// Problem dims (fixed by the reference)
#define TT 4096
#define CC 1024
#define HF 4096
#define NH 16
#define HD 64

// ---------------- scratch (device globals: allocation-free) ----------------
__device__ float g_qkv[(size_t)TT * 3 * CC];
__device__ float g_y  [(size_t)TT * CC];
__device__ float g_x1 [(size_t)TT * CC];
__device__ float g_h1 [(size_t)TT * HF];
__device__ float g_h3 [(size_t)TT * HF];
// pre-split bf16 Q/K/V for attention (hi + lo residual), Q pre-scaled by log2e/8.
__device__ uint4 g_qh[(size_t)TT * CC / 8];
__device__ uint4 g_ql[(size_t)TT * CC / 8];
__device__ uint4 g_kh[(size_t)TT * CC / 8];
__device__ uint4 g_kl[(size_t)TT * CC / 8];
__device__ uint4 g_vh[(size_t)TT * CC / 8];
__device__ uint4 g_vl[(size_t)TT * CC / 8];
// pre-split bf16 GEMM operands
#define NWELEM 16777216ull          // c_attn 3M | c_proj 1M | w1 4M | w3 4M | w2 4M
#define OFF_CATTN 0ull
#define OFF_CPROJ 3145728ull
#define OFF_W1    4194304ull
#define OFF_W3    8388608ull
#define OFF_W2    12582912ull
__device__ uint2 g_wh[NWELEM / 4];  // weight hi
__device__ uint2 g_wl[NWELEM / 4];  // weight lo
__device__ uint2 g_axh[(size_t)TT * CC / 4];   // activation hi (xn / y, reused)
__device__ uint2 g_axl[(size_t)TT * CC / 4];
__device__ uint2 g_hh[(size_t)TT * HF / 4];    // h = silu(h1)*h3 hi
__device__ uint2 g_hl[(size_t)TT * HF / 4];

// ================= helpers =================
__device__ __forceinline__ uint32_t smem_u32(const void* p) {
    uint32_t a;
    asm("{ .reg .u64 t; cvta.to.shared.u64 t, %1; cvt.u32.u64 %0, t; }" : "=r"(a) : "l"(p));
    return a;
}
__device__ __forceinline__ uint32_t cvt2(float a, float b) {
    uint32_t r;
    asm("cvt.rn.satfinite.bf16x2.f32 %0, %1, %2;" : "=r"(r) : "f"(b), "f"(a));
    return r;
}
__device__ __forceinline__ float ex2(float x) {
    float r;
    asm("ex2.approx.f32 %0, %1;" : "=f"(r) : "f"(x));
    return r;
}
__device__ __forceinline__ void mma_bf16(float* c, const uint32_t* a, const uint32_t* b) {
    asm volatile(
        "mma.sync.aligned.m16n8k16.row.col.f32.bf16.bf16.f32 "
        "{%0,%1,%2,%3}, {%4,%5,%6,%7}, {%8,%9}, {%0,%1,%2,%3};"
        : "+f"(c[0]), "+f"(c[1]), "+f"(c[2]), "+f"(c[3])
        : "r"(a[0]), "r"(a[1]), "r"(a[2]), "r"(a[3]), "r"(b[0]), "r"(b[1]));
}
__device__ __forceinline__ void ldsm_x4(uint32_t addr, uint32_t& b0, uint32_t& b1,
                                        uint32_t& b2, uint32_t& b3) {
    asm volatile("ldmatrix.sync.aligned.m8n8.x4.shared.b16 {%0,%1,%2,%3}, [%4];"
                 : "=r"(b0), "=r"(b1), "=r"(b2), "=r"(b3) : "r"(addr));
}
__device__ __forceinline__ void ldsm_x4_trans(uint32_t addr, uint32_t& b0, uint32_t& b1,
                                              uint32_t& b2, uint32_t& b3) {
    asm volatile("ldmatrix.sync.aligned.m8n8.x4.trans.shared.b16 {%0,%1,%2,%3}, [%4];"
                 : "=r"(b0), "=r"(b1), "=r"(b2), "=r"(b3) : "r"(addr));
}
__device__ __forceinline__ void split4(float4 v, uint2& h, uint2& l) {
    h.x = cvt2(v.x, v.y);
    h.y = cvt2(v.z, v.w);
    float r0 = v.x - __uint_as_float(h.x << 16);
    float r1 = v.y - __uint_as_float(h.x & 0xFFFF0000u);
    float r2 = v.z - __uint_as_float(h.y << 16);
    float r3 = v.w - __uint_as_float(h.y & 0xFFFF0000u);
    l.x = cvt2(r0, r1);
    l.y = cvt2(r2, r3);
}
__device__ __forceinline__ void cpa16(uint32_t dst, const void* src) {
    asm volatile("cp.async.cg.shared.global [%0], [%1], 16;" :: "r"(dst), "l"(src) : "memory");
}
#define CP_COMMIT() asm volatile("cp.async.commit_group;" ::: "memory")
#define CP_WAIT0()  asm volatile("cp.async.wait_group 0;" ::: "memory")

// ================= pre-split bf16 GEMM: pure cp.async, 2 CTAs/SM ==============
// C[M,N] = A[M,K] * B[N,K]^T (+ add). Operands already bf16 hi/lo in gmem.
#define TROW 80
#define TILE_BYTES (128 * TROW)
#define STAGE_BYTES (4 * TILE_BYTES)     // Ah, Al, Bh, Bl
#define GEMM_SMEM (2 * STAGE_BYTES)      // 81920

__global__ void __launch_bounds__(256, 2)
gemm_pre(const char* __restrict__ Ah, const char* __restrict__ Al,
         const char* __restrict__ Bh, const char* __restrict__ Bl,
         float* __restrict__ C, int M, int N, int K,
         const float* __restrict__ add) {
    extern __shared__ char smem[];
    const uint32_t sbase = smem_u32(smem);

    const int tid  = threadIdx.x;
    const int warp = tid >> 5;
    const int lane = tid & 31;
    const int g = lane >> 2;
    const int t = lane & 3;
    const int blk = lane >> 3, lr = lane & 7;
    const int wm = warp >> 2;
    const int wn = warp & 3;
    const int m0 = wm * 64;
    const int n0 = wn * 32;
    const int bm = blockIdx.y * 128;
    const int bn = blockIdx.x * 128;
    const size_t K2 = (size_t)K * 2;

    const uint32_t aoff = (uint32_t)((blk & 1) * 8 + lr) * TROW + (uint32_t)(blk >> 1) * 16;
    const uint32_t boff = (uint32_t)((lane >> 4) * 8 + lr) * TROW + (uint32_t)(blk & 1) * 16;

    float acc[4][4][4];
    #pragma unroll
    for (int i = 0; i < 4; i++)
        #pragma unroll
        for (int j = 0; j < 4; j++)
            #pragma unroll
            for (int r = 0; r < 4; r++) acc[i][j][r] = 0.f;

    const int nc = K >> 5;

    auto issue = [&](int c, int st) {
        const uint32_t stg = sbase + (uint32_t)st * STAGE_BYTES;
        const uint32_t cb = (uint32_t)c << 6;
        #pragma unroll
        for (int u = 0; u < 8; u++) {
            int id  = tid + u * 256;
            int ten = id >> 9;            // 0:Ah 1:Al 2:Bh 3:Bl
            int wc  = id & 511;
            int row = wc >> 2, c4 = (wc & 3) * 16;
            const char* base = (ten == 0) ? Ah : (ten == 1) ? Al : (ten == 2) ? Bh : Bl;
            int grow = (ten < 2) ? (bm + row) : (bn + row);
            cpa16(stg + (uint32_t)ten * TILE_BYTES + (uint32_t)row * TROW + c4,
                  base + (size_t)grow * K2 + cb + c4);
        }
        CP_COMMIT();
    };

    issue(0, 0);
    CP_WAIT0();
    __syncthreads();
    if (nc > 1) issue(1, 1);

    for (int c = 0; c < nc; c++) {
        const int cur = c & 1;

        {
            const uint32_t stg = sbase + (uint32_t)cur * STAGE_BYTES;

            uint32_t bh[2][2][4], bl[2][2][4];
            #pragma unroll
            for (int j2 = 0; j2 < 2; j2++)
                #pragma unroll
                for (int ks = 0; ks < 2; ks++) {
                    uint32_t ad = stg + 2 * TILE_BYTES +
                                  (uint32_t)(n0 + j2 * 16) * TROW + boff + ks * 32;
                    ldsm_x4(ad, bh[j2][ks][0], bh[j2][ks][1], bh[j2][ks][2], bh[j2][ks][3]);
                    ldsm_x4(ad + TILE_BYTES, bl[j2][ks][0], bl[j2][ks][1], bl[j2][ks][2], bl[j2][ks][3]);
                }

            #pragma unroll
            for (int i = 0; i < 4; i++) {
                uint32_t ad = stg + (uint32_t)(m0 + i * 16) * TROW + aoff;
                uint32_t ah0[4], ah1[4], al0[4], al1[4];
                ldsm_x4(ad,                     ah0[0], ah0[1], ah0[2], ah0[3]);
                ldsm_x4(ad + 32,                ah1[0], ah1[1], ah1[2], ah1[3]);
                ldsm_x4(ad + TILE_BYTES,        al0[0], al0[1], al0[2], al0[3]);
                ldsm_x4(ad + TILE_BYTES + 32,   al1[0], al1[1], al1[2], al1[3]);
                #pragma unroll
                for (int j2 = 0; j2 < 2; j2++)
                    #pragma unroll
                    for (int jj = 0; jj < 2; jj++) {
                        float* cc = acc[i][j2 * 2 + jj];
                        mma_bf16(cc, ah0, &bh[j2][0][jj * 2]);
                        mma_bf16(cc, al0, &bh[j2][0][jj * 2]);
                        mma_bf16(cc, ah0, &bl[j2][0][jj * 2]);
                        mma_bf16(cc, ah1, &bh[j2][1][jj * 2]);
                        mma_bf16(cc, al1, &bh[j2][1][jj * 2]);
                        mma_bf16(cc, ah1, &bl[j2][1][jj * 2]);
                    }
            }
        }

        if (c + 1 < nc) {
            CP_WAIT0();
            __syncthreads();
            if (c + 2 < nc) issue(c + 2, cur);
        }
    }

    // ---- epilogue
    #pragma unroll
    for (int i = 0; i < 4; i++) {
        size_t r0 = (size_t)(bm + m0 + i * 16 + g);
        size_t r1 = r0 + 8;
        #pragma unroll
        for (int j = 0; j < 4; j++) {
            int col = bn + n0 + j * 8 + t * 2;
            float2 v0 = make_float2(acc[i][j][0], acc[i][j][1]);
            float2 v1 = make_float2(acc[i][j][2], acc[i][j][3]);
            if (add) {
                float2 a0 = *(const float2*)(add + r0 * N + col);
                float2 a1 = *(const float2*)(add + r1 * N + col);
                v0.x += a0.x; v0.y += a0.y;
                v1.x += a1.x; v1.y += a1.y;
            }
            *(float2*)(C + r0 * N + col) = v0;
            *(float2*)(C + r1 * N + col) = v1;
        }
    }
}

// ================= generic fp32 -> bf16 hi/lo split ==============
__global__ void __launch_bounds__(256)
split_f32(const float4* __restrict__ src, uint2* __restrict__ hi,
          uint2* __restrict__ lo, int n4) {
    int i = blockIdx.x * blockDim.x + threadIdx.x;
    if (i < n4) {
        uint2 h, l;
        split4(src[i], h, l);
        hi[i] = h;
        lo[i] = l;
    }
}

// ================= fused RMSNorm + bf16 hi/lo split (no fp32 out) ============
// One block per row; 256 threads x 4 elems (C=1024).
__global__ void __launch_bounds__(256)
rmsnorm_split(const float* __restrict__ x, const float* __restrict__ w,
              uint2* __restrict__ hi, uint2* __restrict__ lo) {
    int row = blockIdx.x;
    int tid = threadIdx.x;
    float4 v = ((const float4*)(x + (size_t)row * CC))[tid];
    float s = v.x * v.x + v.y * v.y + v.z * v.z + v.w * v.w;
    __shared__ float red[32];
    #pragma unroll
    for (int off = 16; off; off >>= 1) s += __shfl_down_sync(0xFFFFFFFFu, s, off);
    if ((tid & 31) == 0) red[tid >> 5] = s;
    __syncthreads();
    if (tid < 32) {
        float vv = (tid < 8) ? red[tid] : 0.f;
        #pragma unroll
        for (int off = 4; off; off >>= 1) vv += __shfl_down_sync(0xFFFFFFFFu, vv, off);
        if (tid == 0) red[0] = vv;
    }
    __syncthreads();
    float inv = rsqrtf(red[0] / (float)CC + 1e-6f);
    float4 wv = ((const float4*)w)[tid];
    v.x *= inv * wv.x; v.y *= inv * wv.y;
    v.z *= inv * wv.z; v.w *= inv * wv.w;
    uint2 h, l;
    split4(v, h, l);
    hi[(size_t)row * 256 + tid] = h;
    lo[(size_t)row * 256 + tid] = l;
}

// ================= SwiGLU with split output ======
__global__ void __launch_bounds__(256)
swiglu_split(const float4* __restrict__ h1, const float4* __restrict__ h3,
             uint2* __restrict__ hh, uint2* __restrict__ hl, int n4) {
    int i = blockIdx.x * blockDim.x + threadIdx.x;
    if (i < n4) {
        float4 a = h1[i];
        float4 b = h3[i];
        a.x = a.x / (1.f + __expf(-a.x)) * b.x;
        a.y = a.y / (1.f + __expf(-a.y)) * b.y;
        a.z = a.z / (1.f + __expf(-a.z)) * b.z;
        a.w = a.w / (1.f + __expf(-a.w)) * b.w;
        uint2 h, l;
        split4(a, h, l);
        hh[i] = h;
        hl[i] = l;
    }
}

// ================= QKV pre-split (Q scaled) =========
__global__ void __launch_bounds__(256)
split_qkv(const float* __restrict__ qkv,
          uint4* __restrict__ qh, uint4* __restrict__ ql,
          uint4* __restrict__ kh, uint4* __restrict__ kl,
          uint4* __restrict__ vh, uint4* __restrict__ vl) {
    const float qs = 1.4426950408889634f * 0.125f;
    int i = blockIdx.x * blockDim.x + threadIdx.x;
    int r  = i >> 7;
    int c8 = (i & 127) * 8;
    const float* base = qkv + (size_t)r * 3 * CC + c8;

    float4 a = *(const float4*)(base);
    float4 b = *(const float4*)(base + 4);
    a.x *= qs; a.y *= qs; a.z *= qs; a.w *= qs;
    b.x *= qs; b.y *= qs; b.z *= qs; b.w *= qs;
    uint2 h0, l0, h1, l1;
    split4(a, h0, l0); split4(b, h1, l1);
    qh[i] = make_uint4(h0.x, h0.y, h1.x, h1.y);
    ql[i] = make_uint4(l0.x, l0.y, l1.x, l1.y);

    a = *(const float4*)(base + CC);
    b = *(const float4*)(base + CC + 4);
    split4(a, h0, l0); split4(b, h1, l1);
    kh[i] = make_uint4(h0.x, h0.y, h1.x, h1.y);
    kl[i] = make_uint4(l0.x, l0.y, l1.x, l1.y);

    a = *(const float4*)(base + 2 * CC);
    b = *(const float4*)(base + 2 * CC + 4);
    split4(a, h0, l0); split4(b, h1, l1);
    vh[i] = make_uint4(h0.x, h0.y, h1.x, h1.y);
    vl[i] = make_uint4(l0.x, l0.y, l1.x, l1.y);
}

// ================= MMA flash attention (unchanged — 356-360us measured) =========
#define ASTR 144
#define QLSM (128 * ASTR)
#define ABUF0 (2 * QLSM)
#define KVT (64 * ASTR)
#define ABUFB (4 * KVT)
#define ATTN_SMEM (ABUF0 + 2 * ABUFB)  // 110592

__global__ void __launch_bounds__(256, 2)
attn_mma(const char* __restrict__ qhc, const char* __restrict__ qlc,
         const char* __restrict__ khc, const char* __restrict__ klc,
         const char* __restrict__ vhc, const char* __restrict__ vlc,
         float* __restrict__ y) {
    extern __shared__ char sm[];
    const uint32_t sb = smem_u32(sm);
    const int tid  = threadIdx.x;
    const int w    = tid >> 5;
    const int lane = tid & 31;
    const int g = lane >> 2, t = lane & 3;
    const int qt = 31 - (int)blockIdx.x;
    const int h  = blockIdx.y;
    const int q0 = qt * 128;
    const int qko = h * HD;

    const int cr = tid >> 3;
    const int ch = tid & 7;
    const size_t rowb = (size_t)2 * CC;

    #pragma unroll
    for (int u = 0; u < 8; u++) {
        int r = (u & 3) * 32 + cr;
        const char* src = ((u >> 2) ? qlc : qhc) + (size_t)(q0 + r) * rowb + qko * 2 + ch * 16;
        cpa16(sb + (u >> 2) * QLSM + (uint32_t)r * ASTR + ch * 16, src);
    }
    #pragma unroll
    for (int u = 0; u < 8; u++) {
        int r = (u & 1) * 32 + cr;
        const char* tp = (u < 2) ? khc : (u < 4) ? klc : (u < 6) ? vhc : vlc;
        const char* src = tp + (size_t)r * rowb + qko * 2 + ch * 16;
        cpa16(sb + ABUF0 + (u >> 1) * KVT + (uint32_t)r * ASTR + ch * 16, src);
    }
    CP_COMMIT();
    CP_WAIT0();
    __syncthreads();

    const int blk = lane >> 3, lr = lane & 7;
    uint32_t qfh[4][4], qfl[4][4];
    {
        uint32_t qa = sb + (uint32_t)(w * 16 + (blk & 1) * 8 + lr) * ASTR + (uint32_t)(blk >> 1) * 16;
        #pragma unroll
        for (int ks = 0; ks < 4; ks++) {
            ldsm_x4(qa + ks * 32,        qfh[ks][0], qfh[ks][1], qfh[ks][2], qfh[ks][3]);
            ldsm_x4(qa + QLSM + ks * 32, qfl[ks][0], qfl[ks][1], qfl[ks][2], qfl[ks][3]);
        }
    }

    float O[8][4];
    #pragma unroll
    for (int nf = 0; nf < 8; nf++)
        #pragma unroll
        for (int r = 0; r < 4; r++) O[nf][r] = 0.f;
    float l0 = 0.f, l1 = 0.f;

    const int nk = 2 * qt + 2;
    const int r0g = q0 + w * 16 + g;
    const uint32_t ldsmV_off = (uint32_t)((blk & 1) * 8 + lr) * ASTR + (uint32_t)(blk >> 1) * 16;
    const uint32_t ldsmK_off = (uint32_t)(((lane >> 4) << 3) | lr) * ASTR + (uint32_t)((blk & 1) * 16);

    for (int kt = 0; kt < nk; kt++) {
        const uint32_t kb = ABUF0 + (uint32_t)(kt & 1) * ABUFB;
        const bool more = (kt + 1 < nk);

        if (more) {
            int k0n = (kt + 1) * 64;
            uint32_t nb = sb + ABUF0 + (uint32_t)((kt + 1) & 1) * ABUFB;
            #pragma unroll
            for (int u = 0; u < 8; u++) {
                int r = (u & 1) * 32 + cr;
                const char* tp = (u < 2) ? khc : (u < 4) ? klc : (u < 6) ? vhc : vlc;
                const char* src = tp + (size_t)(k0n + r) * rowb + qko * 2 + ch * 16;
                cpa16(nb + (u >> 1) * KVT + (uint32_t)r * ASTR + ch * 16, src);
            }
            CP_COMMIT();
        }

        float S[8][4];
        #pragma unroll
        for (int nf = 0; nf < 8; nf++)
            #pragma unroll
            for (int r = 0; r < 4; r++) S[nf][r] = 0.f;

        {
            const uint32_t kh = sb + kb + ldsmK_off;
            #pragma unroll
            for (int ks = 0; ks < 4; ks++) {
                #pragma unroll
                for (int nfp = 0; nfp < 4; nfp++) {
                    uint32_t a = kh + (uint32_t)(nfp * 16) * ASTR + (uint32_t)(ks * 32);
                    uint32_t h0, h1, h2, h3, l0r, l1r, l2r, l3r;
                    ldsm_x4(a, h0, h1, h2, h3);
                    ldsm_x4(a + KVT, l0r, l1r, l2r, l3r);
                    uint32_t bh0[2] = {h0, h1}, bh1[2] = {h2, h3};
                    uint32_t bl0[2] = {l0r, l1r}, bl1[2] = {l2r, l3r};
                    mma_bf16(S[2 * nfp],     qfh[ks], bh0);
                    mma_bf16(S[2 * nfp],     qfl[ks], bh0);
                    mma_bf16(S[2 * nfp],     qfh[ks], bl0);
                    mma_bf16(S[2 * nfp + 1], qfh[ks], bh1);
                    mma_bf16(S[2 * nfp + 1], qfl[ks], bh1);
                    mma_bf16(S[2 * nfp + 1], qfh[ks], bl1);
                }
            }
        }

        if (kt >= 2 * qt) {
            int k0 = kt * 64;
            #pragma unroll
            for (int nf = 0; nf < 8; nf++) {
                int c = k0 + nf * 8 + 2 * t;
                if (c     > r0g)     S[nf][0] = -1e30f;
                if (c + 1 > r0g)     S[nf][1] = -1e30f;
                if (c     > r0g + 8) S[nf][2] = -1e30f;
                if (c + 1 > r0g + 8) S[nf][3] = -1e30f;
            }
        }

        #pragma unroll
        for (int nf = 0; nf < 8; nf++) {
            S[nf][0] = ex2(S[nf][0]);
            S[nf][1] = ex2(S[nf][1]);
            S[nf][2] = ex2(S[nf][2]);
            S[nf][3] = ex2(S[nf][3]);
            l0 += S[nf][0] + S[nf][1];
            l1 += S[nf][2] + S[nf][3];
        }

        {
            const uint32_t vh = sb + kb + 2 * KVT + ldsmV_off;
            #pragma unroll
            for (int ks = 0; ks < 4; ks++) {
                float p00 = S[2 * ks][0], p01 = S[2 * ks][1];
                float p02 = S[2 * ks][2], p03 = S[2 * ks][3];
                float p10 = S[2 * ks + 1][0], p11 = S[2 * ks + 1][1];
                float p12 = S[2 * ks + 1][2], p13 = S[2 * ks + 1][3];
                uint32_t pah[4], pal[4];
                pah[0] = cvt2(p00, p01);
                pah[1] = cvt2(p02, p03);
                pah[2] = cvt2(p10, p11);
                pah[3] = cvt2(p12, p13);
                pal[0] = cvt2(p00 - __uint_as_float(pah[0] << 16),
                              p01 - __uint_as_float(pah[0] & 0xFFFF0000u));
                pal[1] = cvt2(p02 - __uint_as_float(pah[1] << 16),
                              p03 - __uint_as_float(pah[1] & 0xFFFF0000u));
                pal[2] = cvt2(p10 - __uint_as_float(pah[2] << 16),
                              p11 - __uint_as_float(pah[2] & 0xFFFF0000u));
                pal[3] = cvt2(p12 - __uint_as_float(pah[3] << 16),
                              p13 - __uint_as_float(pah[3] & 0xFFFF0000u));

                uint32_t ka = vh + (uint32_t)(ks * 16) * ASTR;
                #pragma unroll
                for (int np = 0; np < 4; np++) {
                    uint32_t a = ka + (uint32_t)np * 32;
                    uint32_t b0, b1, b2, b3;
                    ldsm_x4_trans(a, b0, b1, b2, b3);
                    uint32_t bb0[2] = {b0, b1}, bb1[2] = {b2, b3};
                    mma_bf16(O[2 * np],     pah, bb0);
                    mma_bf16(O[2 * np + 1], pah, bb1);
                    mma_bf16(O[2 * np],     pal, bb0);
                    mma_bf16(O[2 * np + 1], pal, bb1);
                    ldsm_x4_trans(a + KVT, b0, b1, b2, b3);
                    uint32_t cb0[2] = {b0, b1}, cb1[2] = {b2, b3};
                    mma_bf16(O[2 * np],     pah, cb0);
                    mma_bf16(O[2 * np + 1], pah, cb1);
                }
            }
        }

        if (more) CP_WAIT0();
        __syncthreads();
    }

    l0 += __shfl_xor_sync(0xFFFFFFFFu, l0, 1);
    l0 += __shfl_xor_sync(0xFFFFFFFFu, l0, 2);
    l1 += __shfl_xor_sync(0xFFFFFFFFu, l1, 1);
    l1 += __shfl_xor_sync(0xFFFFFFFFu, l1, 2);
    float i0 = 1.f / l0, i1 = 1.f / l1;
    #pragma unroll
    for (int nf = 0; nf < 8; nf++) {
        int col = qko + nf * 8 + 2 * t;
        *(float2*)(y + (size_t)r0g * CC + col) =
            make_float2(O[nf][0] * i0, O[nf][1] * i0);
        *(float2*)(y + (size_t)(r0g + 8) * CC + col) =
            make_float2(O[nf][2] * i1, O[nf][3] * i1);
    }
}

// ---------------- launch ----------------
extern "C" void kernel_launch(void* const* d_in, const int* in_sizes, int n_in,
                              void* d_out, int out_size) {
    const float* x           = (const float*)d_in[0];
    const float* attn_norm_w = (const float*)d_in[1];
    const float* ffn_norm_w  = (const float*)d_in[2];
    const float* c_attn_w    = (const float*)d_in[3];
    const float* c_proj_w    = (const float*)d_in[4];
    const float* w1          = (const float*)d_in[5];
    const float* w2          = (const float*)d_in[6];
    const float* w3          = (const float*)d_in[7];
    float* out = (float*)d_out;

    float *qkv, *yb, *x1, *h1, *h3;
    cudaGetSymbolAddress((void**)&qkv, g_qkv);
    cudaGetSymbolAddress((void**)&yb,  g_y);
    cudaGetSymbolAddress((void**)&x1,  g_x1);
    cudaGetSymbolAddress((void**)&h1,  g_h1);
    cudaGetSymbolAddress((void**)&h3,  g_h3);
    void *qh, *ql, *kh, *kl, *vh, *vl, *whv, *wlv, *axh, *axl, *hh, *hl;
    cudaGetSymbolAddress(&qh, g_qh);
    cudaGetSymbolAddress(&ql, g_ql);
    cudaGetSymbolAddress(&kh, g_kh);
    cudaGetSymbolAddress(&kl, g_kl);
    cudaGetSymbolAddress(&vh, g_vh);
    cudaGetSymbolAddress(&vl, g_vl);
    cudaGetSymbolAddress(&whv, g_wh);
    cudaGetSymbolAddress(&wlv, g_wl);
    cudaGetSymbolAddress(&axh, g_axh);
    cudaGetSymbolAddress(&axl, g_axl);
    cudaGetSymbolAddress(&hh, g_hh);
    cudaGetSymbolAddress(&hl, g_hl);

    const char* whc = (const char*)whv;
    const char* wlc = (const char*)wlv;
    uint2* whu = (uint2*)whv;
    uint2* wlu = (uint2*)wlv;

    cudaFuncSetAttribute(gemm_pre, cudaFuncAttributeMaxDynamicSharedMemorySize, GEMM_SMEM);
    cudaFuncSetAttribute(attn_mma, cudaFuncAttributeMaxDynamicSharedMemorySize, ATTN_SMEM);

    // 0) split weights into bf16 hi/lo
    split_f32<<<(3 * CC * CC / 4) / 256, 256>>>((const float4*)c_attn_w,
        whu + OFF_CATTN / 4, wlu + OFF_CATTN / 4, 3 * CC * CC / 4);
    split_f32<<<(CC * CC / 4) / 256, 256>>>((const float4*)c_proj_w,
        whu + OFF_CPROJ / 4, wlu + OFF_CPROJ / 4, CC * CC / 4);
    split_f32<<<(HF * CC / 4) / 256, 256>>>((const float4*)w1,
        whu + OFF_W1 / 4, wlu + OFF_W1 / 4, HF * CC / 4);
    split_f32<<<(HF * CC / 4) / 256, 256>>>((const float4*)w3,
        whu + OFF_W3 / 4, wlu + OFF_W3 / 4, HF * CC / 4);
    split_f32<<<(CC * HF / 4) / 256, 256>>>((const float4*)w2,
        whu + OFF_W2 / 4, wlu + OFF_W2 / 4, CC * HF / 4);

    // 1) xn = rmsnorm(x, attn_norm_w) -> bf16 hi/lo directly
    rmsnorm_split<<<TT, 256>>>(x, attn_norm_w, (uint2*)axh, (uint2*)axl);

    // 2) qkv = xn @ c_attn_w^T
    gemm_pre<<<dim3(3 * CC / 128, TT / 128), 256, GEMM_SMEM>>>(
        (const char*)axh, (const char*)axl,
        whc + OFF_CATTN * 2, wlc + OFF_CATTN * 2, qkv, TT, 3 * CC, CC, nullptr);

    // 3) pre-split qkv for attention (Q pre-scaled)
    split_qkv<<<TT * CC / 8 / 256, 256>>>(qkv, (uint4*)qh, (uint4*)ql,
                                          (uint4*)kh, (uint4*)kl, (uint4*)vh, (uint4*)vl);

    // 4) y = causal_attention
    attn_mma<<<dim3(TT / 128, NH), 256, ATTN_SMEM>>>(
        (const char*)qh, (const char*)ql, (const char*)kh,
        (const char*)kl, (const char*)vh, (const char*)vl, yb);

    // 5) x1 = y @ c_proj_w^T + x
    split_f32<<<(TT * CC / 4) / 256, 256>>>((const float4*)yb, (uint2*)axh, (uint2*)axl, TT * CC / 4);
    gemm_pre<<<dim3(CC / 128, TT / 128), 256, GEMM_SMEM>>>(
        (const char*)axh, (const char*)axl,
        whc + OFF_CPROJ * 2, wlc + OFF_CPROJ * 2, x1, TT, CC, CC, x);

    // 6) xn = rmsnorm(x1, ffn_norm_w) -> bf16 hi/lo directly
    rmsnorm_split<<<TT, 256>>>(x1, ffn_norm_w, (uint2*)axh, (uint2*)axl);

    // 7) h1 = xn @ w1^T ; h3 = xn @ w3^T
    gemm_pre<<<dim3(HF / 128, TT / 128), 256, GEMM_SMEM>>>(
        (const char*)axh, (const char*)axl,
        whc + OFF_W1 * 2, wlc + OFF_W1 * 2, h1, TT, HF, CC, nullptr);
    gemm_pre<<<dim3(HF / 128, TT / 128), 256, GEMM_SMEM>>>(
        (const char*)axh, (const char*)axl,
        whc + OFF_W3 * 2, wlc + OFF_W3 * 2, h3, TT, HF, CC, nullptr);

    // 8) h = silu(h1) * h3, split output
    swiglu_split<<<(TT * HF / 4) / 256, 256>>>((const float4*)h1, (const float4*)h3,
                                               (uint2*)hh, (uint2*)hl, TT * HF / 4);

    // 9) out = h @ w2^T + x1
    gemm_pre<<<dim3(CC / 128, TT / 128), 256, GEMM_SMEM>>>(
        (const char*)hh, (const char*)hl,
        whc + OFF_W2 * 2, wlc + OFF_W2 * 2, out, TT, CC, HF, x1);
}

// round 16
// speedup vs baseline: 2.1075x; 1.0026x over previous
#include <cuda_runtime.h>
#include <cuda_bf16.h>
#include <cstdint>
#include <math.h>

// Problem dims (fixed by the reference)
#define TT 4096
#define CC 1024
#define HF 4096
#define NH 16
#define HD 64

// ---------------- scratch (device globals: allocation-free) ----------------
__device__ float g_x1 [(size_t)TT * CC];
__device__ float g_h1 [(size_t)TT * HF];
__device__ float g_h3 [(size_t)TT * HF];
// pre-split bf16 Q/K/V for attention (hi + lo residual), Q pre-scaled by log2e/8.
__device__ uint2 g_qh[(size_t)TT * CC / 4];
__device__ uint2 g_ql[(size_t)TT * CC / 4];
__device__ uint2 g_kh[(size_t)TT * CC / 4];
__device__ uint2 g_kl[(size_t)TT * CC / 4];
__device__ uint2 g_vh[(size_t)TT * CC / 4];
__device__ uint2 g_vl[(size_t)TT * CC / 4];
// pre-split bf16 GEMM operands
#define NWELEM 16777216ull          // c_attn 3M | c_proj 1M | w1 4M | w3 4M | w2 4M
#define OFF_CATTN 0ull
#define OFF_CPROJ 3145728ull
#define OFF_W1    4194304ull
#define OFF_W3    8388608ull
#define OFF_W2    12582912ull
__device__ uint2 g_wh[NWELEM / 4];  // weight hi
__device__ uint2 g_wl[NWELEM / 4];  // weight lo
__device__ uint2 g_axh[(size_t)TT * CC / 4];   // activation hi (xn / y, reused)
__device__ uint2 g_axl[(size_t)TT * CC / 4];
__device__ uint2 g_hh[(size_t)TT * HF / 4];    // h = silu(h1)*h3 hi
__device__ uint2 g_hl[(size_t)TT * HF / 4];

// ================= helpers =================
__device__ __forceinline__ uint32_t smem_u32(const void* p) {
    uint32_t a;
    asm("{ .reg .u64 t; cvta.to.shared.u64 t, %1; cvt.u32.u64 %0, t; }" : "=r"(a) : "l"(p));
    return a;
}
__device__ __forceinline__ uint32_t cvt2(float a, float b) {
    uint32_t r;
    asm("cvt.rn.satfinite.bf16x2.f32 %0, %1, %2;" : "=r"(r) : "f"(b), "f"(a));
    return r;
}
__device__ __forceinline__ float ex2(float x) {
    float r;
    asm("ex2.approx.f32 %0, %1;" : "=f"(r) : "f"(x));
    return r;
}
__device__ __forceinline__ void mma_bf16(float* c, const uint32_t* a, const uint32_t* b) {
    asm volatile(
        "mma.sync.aligned.m16n8k16.row.col.f32.bf16.bf16.f32 "
        "{%0,%1,%2,%3}, {%4,%5,%6,%7}, {%8,%9}, {%0,%1,%2,%3};"
        : "+f"(c[0]), "+f"(c[1]), "+f"(c[2]), "+f"(c[3])
        : "r"(a[0]), "r"(a[1]), "r"(a[2]), "r"(a[3]), "r"(b[0]), "r"(b[1]));
}
__device__ __forceinline__ void ldsm_x4(uint32_t addr, uint32_t& b0, uint32_t& b1,
                                        uint32_t& b2, uint32_t& b3) {
    asm volatile("ldmatrix.sync.aligned.m8n8.x4.shared.b16 {%0,%1,%2,%3}, [%4];"
                 : "=r"(b0), "=r"(b1), "=r"(b2), "=r"(b3) : "r"(addr));
}
__device__ __forceinline__ void ldsm_x4_trans(uint32_t addr, uint32_t& b0, uint32_t& b1,
                                              uint32_t& b2, uint32_t& b3) {
    asm volatile("ldmatrix.sync.aligned.m8n8.x4.trans.shared.b16 {%0,%1,%2,%3}, [%4];"
                 : "=r"(b0), "=r"(b1), "=r"(b2), "=r"(b3) : "r"(addr));
}
__device__ __forceinline__ void split4(float4 v, uint2& h, uint2& l) {
    h.x = cvt2(v.x, v.y);
    h.y = cvt2(v.z, v.w);
    float r0 = v.x - __uint_as_float(h.x << 16);
    float r1 = v.y - __uint_as_float(h.x & 0xFFFF0000u);
    float r2 = v.z - __uint_as_float(h.y << 16);
    float r3 = v.w - __uint_as_float(h.y & 0xFFFF0000u);
    l.x = cvt2(r0, r1);
    l.y = cvt2(r2, r3);
}
__device__ __forceinline__ void cpa16(uint32_t dst, const void* src) {
    asm volatile("cp.async.cg.shared.global [%0], [%1], 16;" :: "r"(dst), "l"(src) : "memory");
}
#define CP_COMMIT() asm volatile("cp.async.commit_group;" ::: "memory")
#define CP_WAIT0()  asm volatile("cp.async.wait_group 0;" ::: "memory")

// ================= pre-split bf16 GEMM: pure cp.async, 2 CTAs/SM ==============
// C[M,N] = A[M,K] * B[N,K]^T (+ add). Operands already bf16 hi/lo in gmem.
// SPLITOUT: write bf16 hi/lo to q/k/v arrays by column segment (Q pre-scaled).
#define TROW 80
#define TILE_BYTES (128 * TROW)
#define STAGE_BYTES (4 * TILE_BYTES)
#define GEMM_SMEM (2 * STAGE_BYTES)      // 81920

template<bool SPLITOUT>
__global__ void __launch_bounds__(256, 2)
gemm_pre(const char* __restrict__ Ah, const char* __restrict__ Al,
         const char* __restrict__ Bh, const char* __restrict__ Bl,
         float* __restrict__ C, int M, int N, int K,
         const float* __restrict__ add,
         uint32_t* __restrict__ oqh, uint32_t* __restrict__ oql,
         uint32_t* __restrict__ okh, uint32_t* __restrict__ okl,
         uint32_t* __restrict__ ovh, uint32_t* __restrict__ ovl) {
    extern __shared__ char smem[];
    const uint32_t sbase = smem_u32(smem);

    const int tid  = threadIdx.x;
    const int warp = tid >> 5;
    const int lane = tid & 31;
    const int g = lane >> 2;
    const int t = lane & 3;
    const int blk = lane >> 3, lr = lane & 7;
    const int wm = warp >> 2;
    const int wn = warp & 3;
    const int m0 = wm * 64;
    const int n0 = wn * 32;
    const int bm = blockIdx.y * 128;
    const int bn = blockIdx.x * 128;
    const size_t K2 = (size_t)K * 2;

    const uint32_t aoff = (uint32_t)((blk & 1) * 8 + lr) * TROW + (uint32_t)(blk >> 1) * 16;
    const uint32_t boff = (uint32_t)((lane >> 4) * 8 + lr) * TROW + (uint32_t)(blk & 1) * 16;

    float acc[4][4][4];
    #pragma unroll
    for (int i = 0; i < 4; i++)
        #pragma unroll
        for (int j = 0; j < 4; j++)
            #pragma unroll
            for (int r = 0; r < 4; r++) acc[i][j][r] = 0.f;

    const int nc = K >> 5;

    auto issue = [&](int c, int st) {
        const uint32_t stg = sbase + (uint32_t)st * STAGE_BYTES;
        const uint32_t cb = (uint32_t)c << 6;
        #pragma unroll
        for (int u = 0; u < 8; u++) {
            int id  = tid + u * 256;
            int ten = id >> 9;            // 0:Ah 1:Al 2:Bh 3:Bl
            int wc  = id & 511;
            int row = wc >> 2, c4 = (wc & 3) * 16;
            const char* base = (ten == 0) ? Ah : (ten == 1) ? Al : (ten == 2) ? Bh : Bl;
            int grow = (ten < 2) ? (bm + row) : (bn + row);
            cpa16(stg + (uint32_t)ten * TILE_BYTES + (uint32_t)row * TROW + c4,
                  base + (size_t)grow * K2 + cb + c4);
        }
        CP_COMMIT();
    };

    issue(0, 0);
    CP_WAIT0();
    __syncthreads();
    if (nc > 1) issue(1, 1);

    for (int c = 0; c < nc; c++) {
        const int cur = c & 1;

        {
            const uint32_t stg = sbase + (uint32_t)cur * STAGE_BYTES;

            uint32_t bh[2][2][4], bl[2][2][4];
            #pragma unroll
            for (int j2 = 0; j2 < 2; j2++)
                #pragma unroll
                for (int ks = 0; ks < 2; ks++) {
                    uint32_t ad = stg + 2 * TILE_BYTES +
                                  (uint32_t)(n0 + j2 * 16) * TROW + boff + ks * 32;
                    ldsm_x4(ad, bh[j2][ks][0], bh[j2][ks][1], bh[j2][ks][2], bh[j2][ks][3]);
                    ldsm_x4(ad + TILE_BYTES, bl[j2][ks][0], bl[j2][ks][1], bl[j2][ks][2], bl[j2][ks][3]);
                }

            #pragma unroll
            for (int i = 0; i < 4; i++) {
                uint32_t ad = stg + (uint32_t)(m0 + i * 16) * TROW + aoff;
                uint32_t ah0[4], ah1[4], al0[4], al1[4];
                ldsm_x4(ad,                     ah0[0], ah0[1], ah0[2], ah0[3]);
                ldsm_x4(ad + 32,                ah1[0], ah1[1], ah1[2], ah1[3]);
                ldsm_x4(ad + TILE_BYTES,        al0[0], al0[1], al0[2], al0[3]);
                ldsm_x4(ad + TILE_BYTES + 32,   al1[0], al1[1], al1[2], al1[3]);
                #pragma unroll
                for (int j2 = 0; j2 < 2; j2++)
                    #pragma unroll
                    for (int jj = 0; jj < 2; jj++) {
                        float* cc = acc[i][j2 * 2 + jj];
                        mma_bf16(cc, ah0, &bh[j2][0][jj * 2]);
                        mma_bf16(cc, al0, &bh[j2][0][jj * 2]);
                        mma_bf16(cc, ah0, &bl[j2][0][jj * 2]);
                        mma_bf16(cc, ah1, &bh[j2][1][jj * 2]);
                        mma_bf16(cc, al1, &bh[j2][1][jj * 2]);
                        mma_bf16(cc, ah1, &bl[j2][1][jj * 2]);
                    }
            }
        }

        if (c + 1 < nc) {
            CP_WAIT0();
            __syncthreads();
            if (c + 2 < nc) issue(c + 2, cur);
        }
    }

    // ---- epilogue
    if (SPLITOUT) {
        const int seg = bn >> 10;                // 0=Q, 1=K, 2=V
        uint32_t* hp = seg == 0 ? oqh : (seg == 1 ? okh : ovh);
        uint32_t* lp = seg == 0 ? oql : (seg == 1 ? okl : ovl);
        const float sc = (seg == 0) ? 0.18033688011110918f : 1.f;   // log2e/8
        const int cb = (bn & 1023) + n0;
        #pragma unroll
        for (int i = 0; i < 4; i++) {
            size_t r0 = (size_t)(bm + m0 + i * 16 + g);
            size_t r1 = r0 + 8;
            #pragma unroll
            for (int j = 0; j < 4; j++) {
                int cp = (cb + j * 8 + t * 2) >> 1;
                float v0 = acc[i][j][0] * sc, v1 = acc[i][j][1] * sc;
                float v2 = acc[i][j][2] * sc, v3 = acc[i][j][3] * sc;
                uint32_t h0 = cvt2(v0, v1);
                uint32_t l0 = cvt2(v0 - __uint_as_float(h0 << 16),
                                   v1 - __uint_as_float(h0 & 0xFFFF0000u));
                uint32_t h1 = cvt2(v2, v3);
                uint32_t l1 = cvt2(v2 - __uint_as_float(h1 << 16),
                                   v3 - __uint_as_float(h1 & 0xFFFF0000u));
                hp[r0 * 512 + cp] = h0;
                lp[r0 * 512 + cp] = l0;
                hp[r1 * 512 + cp] = h1;
                lp[r1 * 512 + cp] = l1;
            }
        }
    } else {
        #pragma unroll
        for (int i = 0; i < 4; i++) {
            size_t r0 = (size_t)(bm + m0 + i * 16 + g);
            size_t r1 = r0 + 8;
            #pragma unroll
            for (int j = 0; j < 4; j++) {
                int col = bn + n0 + j * 8 + t * 2;
                float2 v0 = make_float2(acc[i][j][0], acc[i][j][1]);
                float2 v1 = make_float2(acc[i][j][2], acc[i][j][3]);
                if (add) {
                    float2 a0 = *(const float2*)(add + r0 * N + col);
                    float2 a1 = *(const float2*)(add + r1 * N + col);
                    v0.x += a0.x; v0.y += a0.y;
                    v1.x += a1.x; v1.y += a1.y;
                }
                *(float2*)(C + r0 * N + col) = v0;
                *(float2*)(C + r1 * N + col) = v1;
            }
        }
    }
}

// ================= merged weight split: all 5 weights in one launch ==========
__global__ void __launch_bounds__(256)
split_weights(const float4* __restrict__ ca, const float4* __restrict__ cp,
              const float4* __restrict__ w1, const float4* __restrict__ w3,
              const float4* __restrict__ w2,
              uint2* __restrict__ hi, uint2* __restrict__ lo) {
    size_t i = (size_t)blockIdx.x * blockDim.x + threadIdx.x;   // uint2 index
    size_t e = i * 4;
    const float4* src;
    size_t off;
    if (e < OFF_CPROJ)   { src = ca; off = OFF_CATTN; }
    else if (e < OFF_W1) { src = cp; off = OFF_CPROJ; }
    else if (e < OFF_W3) { src = w1; off = OFF_W1; }
    else if (e < OFF_W2) { src = w3; off = OFF_W3; }
    else                 { src = w2; off = OFF_W2; }
    float4 v = src[(e - off) >> 2];
    uint2 h, l;
    split4(v, h, l);
    hi[i] = h;
    lo[i] = l;
}

// ================= fused RMSNorm + bf16 hi/lo split ============
__global__ void __launch_bounds__(256)
rmsnorm_split(const float* __restrict__ x, const float* __restrict__ w,
              uint2* __restrict__ hi, uint2* __restrict__ lo) {
    int row = blockIdx.x;
    int tid = threadIdx.x;
    float4 v = ((const float4*)(x + (size_t)row * CC))[tid];
    float s = v.x * v.x + v.y * v.y + v.z * v.z + v.w * v.w;
    __shared__ float red[32];
    #pragma unroll
    for (int off = 16; off; off >>= 1) s += __shfl_down_sync(0xFFFFFFFFu, s, off);
    if ((tid & 31) == 0) red[tid >> 5] = s;
    __syncthreads();
    if (tid < 32) {
        float vv = (tid < 8) ? red[tid] : 0.f;
        #pragma unroll
        for (int off = 4; off; off >>= 1) vv += __shfl_down_sync(0xFFFFFFFFu, vv, off);
        if (tid == 0) red[0] = vv;
    }
    __syncthreads();
    float inv = rsqrtf(red[0] / (float)CC + 1e-6f);
    float4 wv = ((const float4*)w)[tid];
    v.x *= inv * wv.x; v.y *= inv * wv.y;
    v.z *= inv * wv.z; v.w *= inv * wv.w;
    uint2 h, l;
    split4(v, h, l);
    hi[(size_t)row * 256 + tid] = h;
    lo[(size_t)row * 256 + tid] = l;
}

// ================= SwiGLU with split output ======
__global__ void __launch_bounds__(256)
swiglu_split(const float4* __restrict__ h1, const float4* __restrict__ h3,
             uint2* __restrict__ hh, uint2* __restrict__ hl, int n4) {
    int i = blockIdx.x * blockDim.x + threadIdx.x;
    if (i < n4) {
        float4 a = h1[i];
        float4 b = h3[i];
        a.x = a.x / (1.f + __expf(-a.x)) * b.x;
        a.y = a.y / (1.f + __expf(-a.y)) * b.y;
        a.z = a.z / (1.f + __expf(-a.z)) * b.z;
        a.w = a.w / (1.f + __expf(-a.w)) * b.w;
        uint2 h, l;
        split4(a, h, l);
        hh[i] = h;
        hl[i] = l;
    }
}

// ================= MMA flash attention (split-y output) =========
#define ASTR 144
#define QLSM (128 * ASTR)
#define ABUF0 (2 * QLSM)
#define KVT (64 * ASTR)
#define ABUFB (4 * KVT)
#define ATTN_SMEM (ABUF0 + 2 * ABUFB)  // 110592

__global__ void __launch_bounds__(256, 2)
attn_mma(const char* __restrict__ qhc, const char* __restrict__ qlc,
         const char* __restrict__ khc, const char* __restrict__ klc,
         const char* __restrict__ vhc, const char* __restrict__ vlc,
         uint32_t* __restrict__ yh, uint32_t* __restrict__ yl) {
    extern __shared__ char sm[];
    const uint32_t sb = smem_u32(sm);
    const int tid  = threadIdx.x;
    const int w    = tid >> 5;
    const int lane = tid & 31;
    const int g = lane >> 2, t = lane & 3;
    const int qt = 31 - (int)blockIdx.x;
    const int h  = blockIdx.y;
    const int q0 = qt * 128;
    const int qko = h * HD;

    const int cr = tid >> 3;
    const int ch = tid & 7;
    const size_t rowb = (size_t)2 * CC;

    #pragma unroll
    for (int u = 0; u < 8; u++) {
        int r = (u & 3) * 32 + cr;
        const char* src = ((u >> 2) ? qlc : qhc) + (size_t)(q0 + r) * rowb + qko * 2 + ch * 16;
        cpa16(sb + (u >> 2) * QLSM + (uint32_t)r * ASTR + ch * 16, src);
    }
    #pragma unroll
    for (int u = 0; u < 8; u++) {
        int r = (u & 1) * 32 + cr;
        const char* tp = (u < 2) ? khc : (u < 4) ? klc : (u < 6) ? vhc : vlc;
        const char* src = tp + (size_t)r * rowb + qko * 2 + ch * 16;
        cpa16(sb + ABUF0 + (u >> 1) * KVT + (uint32_t)r * ASTR + ch * 16, src);
    }
    CP_COMMIT();
    CP_WAIT0();
    __syncthreads();

    const int blk = lane >> 3, lr = lane & 7;
    uint32_t qfh[4][4], qfl[4][4];
    {
        uint32_t qa = sb + (uint32_t)(w * 16 + (blk & 1) * 8 + lr) * ASTR + (uint32_t)(blk >> 1) * 16;
        #pragma unroll
        for (int ks = 0; ks < 4; ks++) {
            ldsm_x4(qa + ks * 32,        qfh[ks][0], qfh[ks][1], qfh[ks][2], qfh[ks][3]);
            ldsm_x4(qa + QLSM + ks * 32, qfl[ks][0], qfl[ks][1], qfl[ks][2], qfl[ks][3]);
        }
    }

    float O[8][4];
    #pragma unroll
    for (int nf = 0; nf < 8; nf++)
        #pragma unroll
        for (int r = 0; r < 4; r++) O[nf][r] = 0.f;
    float l0 = 0.f, l1 = 0.f;

    const int nk = 2 * qt + 2;
    const int r0g = q0 + w * 16 + g;
    const uint32_t ldsmV_off = (uint32_t)((blk & 1) * 8 + lr) * ASTR + (uint32_t)(blk >> 1) * 16;
    const uint32_t ldsmK_off = (uint32_t)(((lane >> 4) << 3) | lr) * ASTR + (uint32_t)((blk & 1) * 16);

    for (int kt = 0; kt < nk; kt++) {
        const uint32_t kb = ABUF0 + (uint32_t)(kt & 1) * ABUFB;
        const bool more = (kt + 1 < nk);

        if (more) {
            int k0n = (kt + 1) * 64;
            uint32_t nb = sb + ABUF0 + (uint32_t)((kt + 1) & 1) * ABUFB;
            #pragma unroll
            for (int u = 0; u < 8; u++) {
                int r = (u & 1) * 32 + cr;
                const char* tp = (u < 2) ? khc : (u < 4) ? klc : (u < 6) ? vhc : vlc;
                const char* src = tp + (size_t)(k0n + r) * rowb + qko * 2 + ch * 16;
                cpa16(nb + (u >> 1) * KVT + (uint32_t)r * ASTR + ch * 16, src);
            }
            CP_COMMIT();
        }

        float S[8][4];
        #pragma unroll
        for (int nf = 0; nf < 8; nf++)
            #pragma unroll
            for (int r = 0; r < 4; r++) S[nf][r] = 0.f;

        {
            const uint32_t kh = sb + kb + ldsmK_off;
            #pragma unroll
            for (int ks = 0; ks < 4; ks++) {
                #pragma unroll
                for (int nfp = 0; nfp < 4; nfp++) {
                    uint32_t a = kh + (uint32_t)(nfp * 16) * ASTR + (uint32_t)(ks * 32);
                    uint32_t h0, h1, h2, h3, l0r, l1r, l2r, l3r;
                    ldsm_x4(a, h0, h1, h2, h3);
                    ldsm_x4(a + KVT, l0r, l1r, l2r, l3r);
                    uint32_t bh0[2] = {h0, h1}, bh1[2] = {h2, h3};
                    uint32_t bl0[2] = {l0r, l1r}, bl1[2] = {l2r, l3r};
                    mma_bf16(S[2 * nfp],     qfh[ks], bh0);
                    mma_bf16(S[2 * nfp],     qfl[ks], bh0);
                    mma_bf16(S[2 * nfp],     qfh[ks], bl0);
                    mma_bf16(S[2 * nfp + 1], qfh[ks], bh1);
                    mma_bf16(S[2 * nfp + 1], qfl[ks], bh1);
                    mma_bf16(S[2 * nfp + 1], qfh[ks], bl1);
                }
            }
        }

        if (kt >= 2 * qt) {
            int k0 = kt * 64;
            #pragma unroll
            for (int nf = 0; nf < 8; nf++) {
                int c = k0 + nf * 8 + 2 * t;
                if (c     > r0g)     S[nf][0] = -1e30f;
                if (c + 1 > r0g)     S[nf][1] = -1e30f;
                if (c     > r0g + 8) S[nf][2] = -1e30f;
                if (c + 1 > r0g + 8) S[nf][3] = -1e30f;
            }
        }

        #pragma unroll
        for (int nf = 0; nf < 8; nf++) {
            S[nf][0] = ex2(S[nf][0]);
            S[nf][1] = ex2(S[nf][1]);
            S[nf][2] = ex2(S[nf][2]);
            S[nf][3] = ex2(S[nf][3]);
            l0 += S[nf][0] + S[nf][1];
            l1 += S[nf][2] + S[nf][3];
        }

        {
            const uint32_t vh = sb + kb + 2 * KVT + ldsmV_off;
            #pragma unroll
            for (int ks = 0; ks < 4; ks++) {
                float p00 = S[2 * ks][0], p01 = S[2 * ks][1];
                float p02 = S[2 * ks][2], p03 = S[2 * ks][3];
                float p10 = S[2 * ks + 1][0], p11 = S[2 * ks + 1][1];
                float p12 = S[2 * ks + 1][2], p13 = S[2 * ks + 1][3];
                uint32_t pah[4], pal[4];
                pah[0] = cvt2(p00, p01);
                pah[1] = cvt2(p02, p03);
                pah[2] = cvt2(p10, p11);
                pah[3] = cvt2(p12, p13);
                pal[0] = cvt2(p00 - __uint_as_float(pah[0] << 16),
                              p01 - __uint_as_float(pah[0] & 0xFFFF0000u));
                pal[1] = cvt2(p02 - __uint_as_float(pah[1] << 16),
                              p03 - __uint_as_float(pah[1] & 0xFFFF0000u));
                pal[2] = cvt2(p10 - __uint_as_float(pah[2] << 16),
                              p11 - __uint_as_float(pah[2] & 0xFFFF0000u));
                pal[3] = cvt2(p12 - __uint_as_float(pah[3] << 16),
                              p13 - __uint_as_float(pah[3] & 0xFFFF0000u));

                uint32_t ka = vh + (uint32_t)(ks * 16) * ASTR;
                #pragma unroll
                for (int np = 0; np < 4; np++) {
                    uint32_t a = ka + (uint32_t)np * 32;
                    uint32_t b0, b1, b2, b3;
                    ldsm_x4_trans(a, b0, b1, b2, b3);
                    uint32_t bb0[2] = {b0, b1}, bb1[2] = {b2, b3};
                    mma_bf16(O[2 * np],     pah, bb0);
                    mma_bf16(O[2 * np + 1], pah, bb1);
                    mma_bf16(O[2 * np],     pal, bb0);
                    mma_bf16(O[2 * np + 1], pal, bb1);
                    ldsm_x4_trans(a + KVT, b0, b1, b2, b3);
                    uint32_t cb0[2] = {b0, b1}, cb1[2] = {b2, b3};
                    mma_bf16(O[2 * np],     pah, cb0);
                    mma_bf16(O[2 * np + 1], pah, cb1);
                }
            }
        }

        if (more) CP_WAIT0();
        __syncthreads();
    }

    // ---- epilogue: write y directly as bf16 hi/lo (row stride 512 uint32)
    l0 += __shfl_xor_sync(0xFFFFFFFFu, l0, 1);
    l0 += __shfl_xor_sync(0xFFFFFFFFu, l0, 2);
    l1 += __shfl_xor_sync(0xFFFFFFFFu, l1, 1);
    l1 += __shfl_xor_sync(0xFFFFFFFFu, l1, 2);
    float i0 = 1.f / l0, i1 = 1.f / l1;
    #pragma unroll
    for (int nf = 0; nf < 8; nf++) {
        int cp = (qko >> 1) + nf * 4 + t;
        float o0 = O[nf][0] * i0, o1 = O[nf][1] * i0;
        float o2 = O[nf][2] * i1, o3 = O[nf][3] * i1;
        uint32_t h0 = cvt2(o0, o1);
        uint32_t l0w = cvt2(o0 - __uint_as_float(h0 << 16),
                            o1 - __uint_as_float(h0 & 0xFFFF0000u));
        uint32_t h1 = cvt2(o2, o3);
        uint32_t l1w = cvt2(o2 - __uint_as_float(h1 << 16),
                            o3 - __uint_as_float(h1 & 0xFFFF0000u));
        yh[(size_t)r0g * 512 + cp]       = h0;
        yl[(size_t)r0g * 512 + cp]       = l0w;
        yh[(size_t)(r0g + 8) * 512 + cp] = h1;
        yl[(size_t)(r0g + 8) * 512 + cp] = l1w;
    }
}

// ---------------- launch ----------------
extern "C" void kernel_launch(void* const* d_in, const int* in_sizes, int n_in,
                              void* d_out, int out_size) {
    const float* x           = (const float*)d_in[0];
    const float* attn_norm_w = (const float*)d_in[1];
    const float* ffn_norm_w  = (const float*)d_in[2];
    const float* c_attn_w    = (const float*)d_in[3];
    const float* c_proj_w    = (const float*)d_in[4];
    const float* w1          = (const float*)d_in[5];
    const float* w2          = (const float*)d_in[6];
    const float* w3          = (const float*)d_in[7];
    float* out = (float*)d_out;

    float *x1, *h1, *h3;
    cudaGetSymbolAddress((void**)&x1,  g_x1);
    cudaGetSymbolAddress((void**)&h1,  g_h1);
    cudaGetSymbolAddress((void**)&h3,  g_h3);
    void *qh, *ql, *kh, *kl, *vh, *vl, *whv, *wlv, *axh, *axl, *hh, *hl;
    cudaGetSymbolAddress(&qh, g_qh);
    cudaGetSymbolAddress(&ql, g_ql);
    cudaGetSymbolAddress(&kh, g_kh);
    cudaGetSymbolAddress(&kl, g_kl);
    cudaGetSymbolAddress(&vh, g_vh);
    cudaGetSymbolAddress(&vl, g_vl);
    cudaGetSymbolAddress(&whv, g_wh);
    cudaGetSymbolAddress(&wlv, g_wl);
    cudaGetSymbolAddress(&axh, g_axh);
    cudaGetSymbolAddress(&axl, g_axl);
    cudaGetSymbolAddress(&hh, g_hh);
    cudaGetSymbolAddress(&hl, g_hl);

    const char* whc = (const char*)whv;
    const char* wlc = (const char*)wlv;

    cudaFuncSetAttribute(gemm_pre<false>, cudaFuncAttributeMaxDynamicSharedMemorySize, GEMM_SMEM);
    cudaFuncSetAttribute(gemm_pre<true>,  cudaFuncAttributeMaxDynamicSharedMemorySize, GEMM_SMEM);
    cudaFuncSetAttribute(attn_mma, cudaFuncAttributeMaxDynamicSharedMemorySize, ATTN_SMEM);

    // 0) split all weights into bf16 hi/lo (single launch)
    split_weights<<<(int)(NWELEM / 4 / 256), 256>>>(
        (const float4*)c_attn_w, (const float4*)c_proj_w,
        (const float4*)w1, (const float4*)w3, (const float4*)w2,
        (uint2*)whv, (uint2*)wlv);

    // 1) xn = rmsnorm(x, attn_norm_w) -> bf16 hi/lo
    rmsnorm_split<<<TT, 256>>>(x, attn_norm_w, (uint2*)axh, (uint2*)axl);

    // 2) qkv GEMM, split output directly into q/k/v bf16 arrays (Q scaled)
    gemm_pre<true><<<dim3(3 * CC / 128, TT / 128), 256, GEMM_SMEM>>>(
        (const char*)axh, (const char*)axl,
        whc + OFF_CATTN * 2, wlc + OFF_CATTN * 2, nullptr, TT, 3 * CC, CC, nullptr,
        (uint32_t*)qh, (uint32_t*)ql, (uint32_t*)kh, (uint32_t*)kl,
        (uint32_t*)vh, (uint32_t*)vl);

    // 3) y = causal_attention -> split bf16 y (into ax buffers)
    attn_mma<<<dim3(TT / 128, NH), 256, ATTN_SMEM>>>(
        (const char*)qh, (const char*)ql, (const char*)kh,
        (const char*)kl, (const char*)vh, (const char*)vl,
        (uint32_t*)axh, (uint32_t*)axl);

    // 4) x1 = y @ c_proj_w^T + x
    gemm_pre<false><<<dim3(CC / 128, TT / 128), 256, GEMM_SMEM>>>(
        (const char*)axh, (const char*)axl,
        whc + OFF_CPROJ * 2, wlc + OFF_CPROJ * 2, x1, TT, CC, CC, x,
        nullptr, nullptr, nullptr, nullptr, nullptr, nullptr);

    // 5) xn = rmsnorm(x1, ffn_norm_w) -> bf16 hi/lo
    rmsnorm_split<<<TT, 256>>>(x1, ffn_norm_w, (uint2*)axh, (uint2*)axl);

    // 6) h1 = xn @ w1^T ; h3 = xn @ w3^T
    gemm_pre<false><<<dim3(HF / 128, TT / 128), 256, GEMM_SMEM>>>(
        (const char*)axh, (const char*)axl,
        whc + OFF_W1 * 2, wlc + OFF_W1 * 2, h1, TT, HF, CC, nullptr,
        nullptr, nullptr, nullptr, nullptr, nullptr, nullptr);
    gemm_pre<false><<<dim3(HF / 128, TT / 128), 256, GEMM_SMEM>>>(
        (const char*)axh, (const char*)axl,
        whc + OFF_W3 * 2, wlc + OFF_W3 * 2, h3, TT, HF, CC, nullptr,
        nullptr, nullptr, nullptr, nullptr, nullptr, nullptr);

    // 7) h = silu(h1) * h3, split output
    swiglu_split<<<(TT * HF / 4) / 256, 256>>>((const float4*)h1, (const float4*)h3,
                                               (uint2*)hh, (uint2*)hl, TT * HF / 4);

    // 8) out = h @ w2^T + x1
    gemm_pre<false><<<dim3(CC / 128, TT / 128), 256, GEMM_SMEM>>>(
        (const char*)hh, (const char*)hl,
        whc + OFF_W2 * 2, wlc + OFF_W2 * 2, out, TT, CC, HF, x1,
        nullptr, nullptr, nullptr, nullptr, nullptr, nullptr);
}

// round 17
// speedup vs baseline: 2.2781x; 1.0809x over previous
#include <cuda_runtime.h>
#include <cuda_bf16.h>
#include <cstdint>
#include <math.h>

// Problem dims (fixed by the reference)
#define TT 4096
#define CC 1024
#define HF 4096
#define NH 16
#define HD 64

// ---------------- scratch (device globals: allocation-free) ----------------
__device__ float g_x1 [(size_t)TT * CC];
__device__ float g_h1 [(size_t)TT * HF];
__device__ float g_h3 [(size_t)TT * HF];
// pre-split bf16 Q (hi+lo, pre-scaled by log2e/8); K,V bf16 hi only.
__device__ uint2 g_qh[(size_t)TT * CC / 4];
__device__ uint2 g_ql[(size_t)TT * CC / 4];
__device__ uint2 g_kh[(size_t)TT * CC / 4];
__device__ uint2 g_vh[(size_t)TT * CC / 4];
// pre-split bf16 GEMM operands
#define NWELEM 16777216ull          // c_attn 3M | c_proj 1M | w1 4M | w3 4M | w2 4M
#define OFF_CATTN 0ull
#define OFF_CPROJ 3145728ull
#define OFF_W1    4194304ull
#define OFF_W3    8388608ull
#define OFF_W2    12582912ull
__device__ uint2 g_wh[NWELEM / 4];  // weight hi
__device__ uint2 g_wl[NWELEM / 4];  // weight lo
__device__ uint2 g_axh[(size_t)TT * CC / 4];   // activation hi (xn / y, reused)
__device__ uint2 g_axl[(size_t)TT * CC / 4];
__device__ uint2 g_hh[(size_t)TT * HF / 4];    // h = silu(h1)*h3 hi
__device__ uint2 g_hl[(size_t)TT * HF / 4];

// ================= helpers =================
__device__ __forceinline__ uint32_t smem_u32(const void* p) {
    uint32_t a;
    asm("{ .reg .u64 t; cvta.to.shared.u64 t, %1; cvt.u32.u64 %0, t; }" : "=r"(a) : "l"(p));
    return a;
}
__device__ __forceinline__ uint32_t cvt2(float a, float b) {
    uint32_t r;
    asm("cvt.rn.satfinite.bf16x2.f32 %0, %1, %2;" : "=r"(r) : "f"(b), "f"(a));
    return r;
}
__device__ __forceinline__ float ex2(float x) {
    float r;
    asm("ex2.approx.f32 %0, %1;" : "=f"(r) : "f"(x));
    return r;
}
__device__ __forceinline__ void mma_bf16(float* c, const uint32_t* a, const uint32_t* b) {
    asm volatile(
        "mma.sync.aligned.m16n8k16.row.col.f32.bf16.bf16.f32 "
        "{%0,%1,%2,%3}, {%4,%5,%6,%7}, {%8,%9}, {%0,%1,%2,%3};"
        : "+f"(c[0]), "+f"(c[1]), "+f"(c[2]), "+f"(c[3])
        : "r"(a[0]), "r"(a[1]), "r"(a[2]), "r"(a[3]), "r"(b[0]), "r"(b[1]));
}
__device__ __forceinline__ void ldsm_x4(uint32_t addr, uint32_t& b0, uint32_t& b1,
                                        uint32_t& b2, uint32_t& b3) {
    asm volatile("ldmatrix.sync.aligned.m8n8.x4.shared.b16 {%0,%1,%2,%3}, [%4];"
                 : "=r"(b0), "=r"(b1), "=r"(b2), "=r"(b3) : "r"(addr));
}
__device__ __forceinline__ void ldsm_x4_trans(uint32_t addr, uint32_t& b0, uint32_t& b1,
                                              uint32_t& b2, uint32_t& b3) {
    asm volatile("ldmatrix.sync.aligned.m8n8.x4.trans.shared.b16 {%0,%1,%2,%3}, [%4];"
                 : "=r"(b0), "=r"(b1), "=r"(b2), "=r"(b3) : "r"(addr));
}
__device__ __forceinline__ void split4(float4 v, uint2& h, uint2& l) {
    h.x = cvt2(v.x, v.y);
    h.y = cvt2(v.z, v.w);
    float r0 = v.x - __uint_as_float(h.x << 16);
    float r1 = v.y - __uint_as_float(h.x & 0xFFFF0000u);
    float r2 = v.z - __uint_as_float(h.y << 16);
    float r3 = v.w - __uint_as_float(h.y & 0xFFFF0000u);
    l.x = cvt2(r0, r1);
    l.y = cvt2(r2, r3);
}
__device__ __forceinline__ void cpa16(uint32_t dst, const void* src) {
    asm volatile("cp.async.cg.shared.global [%0], [%1], 16;" :: "r"(dst), "l"(src) : "memory");
}
#define CP_COMMIT() asm volatile("cp.async.commit_group;" ::: "memory")
#define CP_WAIT0()  asm volatile("cp.async.wait_group 0;" ::: "memory")

// ================= pre-split bf16 GEMM: pure cp.async, 2 CTAs/SM ==============
// C[M,N] = A[M,K] * B[N,K]^T (+ add). Operands bf16 hi/lo in gmem. 3-term split.
// SPLITOUT: qkv epilogue -> Q hi+lo (scaled), K hi, V hi.
#define TROW 80
#define TILE_BYTES (128 * TROW)
#define STAGE_BYTES (4 * TILE_BYTES)
#define GEMM_SMEM (2 * STAGE_BYTES)      // 81920

template<bool SPLITOUT>
__global__ void __launch_bounds__(256, 2)
gemm_pre(const char* __restrict__ Ah, const char* __restrict__ Al,
         const char* __restrict__ Bh, const char* __restrict__ Bl,
         float* __restrict__ C, int M, int N, int K,
         const float* __restrict__ add,
         uint32_t* __restrict__ oqh, uint32_t* __restrict__ oql,
         uint32_t* __restrict__ okh, uint32_t* __restrict__ ovh) {
    extern __shared__ char smem[];
    const uint32_t sbase = smem_u32(smem);

    const int tid  = threadIdx.x;
    const int warp = tid >> 5;
    const int lane = tid & 31;
    const int g = lane >> 2;
    const int t = lane & 3;
    const int blk = lane >> 3, lr = lane & 7;
    const int wm = warp >> 2;
    const int wn = warp & 3;
    const int m0 = wm * 64;
    const int n0 = wn * 32;
    const int bm = blockIdx.y * 128;
    const int bn = blockIdx.x * 128;
    const size_t K2 = (size_t)K * 2;

    const uint32_t aoff = (uint32_t)((blk & 1) * 8 + lr) * TROW + (uint32_t)(blk >> 1) * 16;
    const uint32_t boff = (uint32_t)((lane >> 4) * 8 + lr) * TROW + (uint32_t)(blk & 1) * 16;

    float acc[4][4][4];
    #pragma unroll
    for (int i = 0; i < 4; i++)
        #pragma unroll
        for (int j = 0; j < 4; j++)
            #pragma unroll
            for (int r = 0; r < 4; r++) acc[i][j][r] = 0.f;

    const int nc = K >> 5;

    auto issue = [&](int c, int st) {
        const uint32_t stg = sbase + (uint32_t)st * STAGE_BYTES;
        const uint32_t cb = (uint32_t)c << 6;
        #pragma unroll
        for (int u = 0; u < 8; u++) {
            int id  = tid + u * 256;
            int ten = id >> 9;            // 0:Ah 1:Al 2:Bh 3:Bl
            int wc  = id & 511;
            int row = wc >> 2, c4 = (wc & 3) * 16;
            const char* base = (ten == 0) ? Ah : (ten == 1) ? Al : (ten == 2) ? Bh : Bl;
            int grow = (ten < 2) ? (bm + row) : (bn + row);
            cpa16(stg + (uint32_t)ten * TILE_BYTES + (uint32_t)row * TROW + c4,
                  base + (size_t)grow * K2 + cb + c4);
        }
        CP_COMMIT();
    };

    issue(0, 0);
    CP_WAIT0();
    __syncthreads();
    if (nc > 1) issue(1, 1);

    for (int c = 0; c < nc; c++) {
        const int cur = c & 1;

        {
            const uint32_t stg = sbase + (uint32_t)cur * STAGE_BYTES;

            uint32_t bh[2][2][4], bl[2][2][4];
            #pragma unroll
            for (int j2 = 0; j2 < 2; j2++)
                #pragma unroll
                for (int ks = 0; ks < 2; ks++) {
                    uint32_t ad = stg + 2 * TILE_BYTES +
                                  (uint32_t)(n0 + j2 * 16) * TROW + boff + ks * 32;
                    ldsm_x4(ad, bh[j2][ks][0], bh[j2][ks][1], bh[j2][ks][2], bh[j2][ks][3]);
                    ldsm_x4(ad + TILE_BYTES, bl[j2][ks][0], bl[j2][ks][1], bl[j2][ks][2], bl[j2][ks][3]);
                }

            #pragma unroll
            for (int i = 0; i < 4; i++) {
                uint32_t ad = stg + (uint32_t)(m0 + i * 16) * TROW + aoff;
                uint32_t ah0[4], ah1[4], al0[4], al1[4];
                ldsm_x4(ad,                     ah0[0], ah0[1], ah0[2], ah0[3]);
                ldsm_x4(ad + 32,                ah1[0], ah1[1], ah1[2], ah1[3]);
                ldsm_x4(ad + TILE_BYTES,        al0[0], al0[1], al0[2], al0[3]);
                ldsm_x4(ad + TILE_BYTES + 32,   al1[0], al1[1], al1[2], al1[3]);
                #pragma unroll
                for (int j2 = 0; j2 < 2; j2++)
                    #pragma unroll
                    for (int jj = 0; jj < 2; jj++) {
                        float* cc = acc[i][j2 * 2 + jj];
                        mma_bf16(cc, ah0, &bh[j2][0][jj * 2]);
                        mma_bf16(cc, al0, &bh[j2][0][jj * 2]);
                        mma_bf16(cc, ah0, &bl[j2][0][jj * 2]);
                        mma_bf16(cc, ah1, &bh[j2][1][jj * 2]);
                        mma_bf16(cc, al1, &bh[j2][1][jj * 2]);
                        mma_bf16(cc, ah1, &bl[j2][1][jj * 2]);
                    }
            }
        }

        if (c + 1 < nc) {
            CP_WAIT0();
            __syncthreads();
            if (c + 2 < nc) issue(c + 2, cur);
        }
    }

    // ---- epilogue
    if (SPLITOUT) {
        const int seg = bn >> 10;                // 0=Q, 1=K, 2=V
        uint32_t* hp = seg == 0 ? oqh : (seg == 1 ? okh : ovh);
        const float sc = (seg == 0) ? 0.18033688011110918f : 1.f;   // log2e/8
        const int cb = (bn & 1023) + n0;
        #pragma unroll
        for (int i = 0; i < 4; i++) {
            size_t r0 = (size_t)(bm + m0 + i * 16 + g);
            size_t r1 = r0 + 8;
            #pragma unroll
            for (int j = 0; j < 4; j++) {
                int cp = (cb + j * 8 + t * 2) >> 1;
                float v0 = acc[i][j][0] * sc, v1 = acc[i][j][1] * sc;
                float v2 = acc[i][j][2] * sc, v3 = acc[i][j][3] * sc;
                uint32_t h0 = cvt2(v0, v1);
                uint32_t h1 = cvt2(v2, v3);
                hp[r0 * 512 + cp] = h0;
                hp[r1 * 512 + cp] = h1;
                if (seg == 0) {
                    uint32_t l0 = cvt2(v0 - __uint_as_float(h0 << 16),
                                       v1 - __uint_as_float(h0 & 0xFFFF0000u));
                    uint32_t l1 = cvt2(v2 - __uint_as_float(h1 << 16),
                                       v3 - __uint_as_float(h1 & 0xFFFF0000u));
                    oql[r0 * 512 + cp] = l0;
                    oql[r1 * 512 + cp] = l1;
                }
            }
        }
    } else {
        #pragma unroll
        for (int i = 0; i < 4; i++) {
            size_t r0 = (size_t)(bm + m0 + i * 16 + g);
            size_t r1 = r0 + 8;
            #pragma unroll
            for (int j = 0; j < 4; j++) {
                int col = bn + n0 + j * 8 + t * 2;
                float2 v0 = make_float2(acc[i][j][0], acc[i][j][1]);
                float2 v1 = make_float2(acc[i][j][2], acc[i][j][3]);
                if (add) {
                    float2 a0 = *(const float2*)(add + r0 * N + col);
                    float2 a1 = *(const float2*)(add + r1 * N + col);
                    v0.x += a0.x; v0.y += a0.y;
                    v1.x += a1.x; v1.y += a1.y;
                }
                *(float2*)(C + r0 * N + col) = v0;
                *(float2*)(C + r1 * N + col) = v1;
            }
        }
    }
}

// ================= merged weight split ==========
__global__ void __launch_bounds__(256)
split_weights(const float4* __restrict__ ca, const float4* __restrict__ cp,
              const float4* __restrict__ w1, const float4* __restrict__ w3,
              const float4* __restrict__ w2,
              uint2* __restrict__ hi, uint2* __restrict__ lo) {
    size_t i = (size_t)blockIdx.x * blockDim.x + threadIdx.x;
    size_t e = i * 4;
    const float4* src;
    size_t off;
    if (e < OFF_CPROJ)   { src = ca; off = OFF_CATTN; }
    else if (e < OFF_W1) { src = cp; off = OFF_CPROJ; }
    else if (e < OFF_W3) { src = w1; off = OFF_W1; }
    else if (e < OFF_W2) { src = w3; off = OFF_W3; }
    else                 { src = w2; off = OFF_W2; }
    float4 v = src[(e - off) >> 2];
    uint2 h, l;
    split4(v, h, l);
    hi[i] = h;
    lo[i] = l;
}

// ================= fused RMSNorm + bf16 hi/lo split ============
__global__ void __launch_bounds__(256)
rmsnorm_split(const float* __restrict__ x, const float* __restrict__ w,
              uint2* __restrict__ hi, uint2* __restrict__ lo) {
    int row = blockIdx.x;
    int tid = threadIdx.x;
    float4 v = ((const float4*)(x + (size_t)row * CC))[tid];
    float s = v.x * v.x + v.y * v.y + v.z * v.z + v.w * v.w;
    __shared__ float red[32];
    #pragma unroll
    for (int off = 16; off; off >>= 1) s += __shfl_down_sync(0xFFFFFFFFu, s, off);
    if ((tid & 31) == 0) red[tid >> 5] = s;
    __syncthreads();
    if (tid < 32) {
        float vv = (tid < 8) ? red[tid] : 0.f;
        #pragma unroll
        for (int off = 4; off; off >>= 1) vv += __shfl_down_sync(0xFFFFFFFFu, vv, off);
        if (tid == 0) red[0] = vv;
    }
    __syncthreads();
    float inv = rsqrtf(red[0] / (float)CC + 1e-6f);
    float4 wv = ((const float4*)w)[tid];
    v.x *= inv * wv.x; v.y *= inv * wv.y;
    v.z *= inv * wv.z; v.w *= inv * wv.w;
    uint2 h, l;
    split4(v, h, l);
    hi[(size_t)row * 256 + tid] = h;
    lo[(size_t)row * 256 + tid] = l;
}

// ================= SwiGLU with split output ======
__global__ void __launch_bounds__(256)
swiglu_split(const float4* __restrict__ h1, const float4* __restrict__ h3,
             uint2* __restrict__ hh, uint2* __restrict__ hl, int n4) {
    int i = blockIdx.x * blockDim.x + threadIdx.x;
    if (i < n4) {
        float4 a = h1[i];
        float4 b = h3[i];
        a.x = a.x / (1.f + __expf(-a.x)) * b.x;
        a.y = a.y / (1.f + __expf(-a.y)) * b.y;
        a.z = a.z / (1.f + __expf(-a.z)) * b.z;
        a.w = a.w / (1.f + __expf(-a.w)) * b.w;
        uint2 h, l;
        split4(a, h, l);
        hh[i] = h;
        hl[i] = l;
    }
}

// ================= MMA flash attention: 4-operand (Qh,Ql,Kh,Vh) =========
// QK = Qh*Kh + Ql*Kh (K bf16); PV = Ph*Vh + Pl*Vh (V bf16, P hi+lo).
#define ASTR 144
#define QLSM (128 * ASTR)
#define ABUF0 (2 * QLSM)
#define KVT (64 * ASTR)
#define ABUFB (2 * KVT)                    // KH, VH only
#define ATTN_SMEM (ABUF0 + 2 * ABUFB)      // 73728

__global__ void __launch_bounds__(256, 2)
attn_mma(const char* __restrict__ qhc, const char* __restrict__ qlc,
         const char* __restrict__ khc, const char* __restrict__ vhc,
         uint32_t* __restrict__ yh, uint32_t* __restrict__ yl) {
    extern __shared__ char sm[];
    const uint32_t sb = smem_u32(sm);
    const int tid  = threadIdx.x;
    const int w    = tid >> 5;
    const int lane = tid & 31;
    const int g = lane >> 2, t = lane & 3;
    const int qt = 31 - (int)blockIdx.x;
    const int h  = blockIdx.y;
    const int q0 = qt * 128;
    const int qko = h * HD;

    const int cr = tid >> 3;
    const int ch = tid & 7;
    const size_t rowb = (size_t)2 * CC;

    #pragma unroll
    for (int u = 0; u < 8; u++) {            // Q hi+lo
        int r = (u & 3) * 32 + cr;
        const char* src = ((u >> 2) ? qlc : qhc) + (size_t)(q0 + r) * rowb + qko * 2 + ch * 16;
        cpa16(sb + (u >> 2) * QLSM + (uint32_t)r * ASTR + ch * 16, src);
    }
    #pragma unroll
    for (int u = 0; u < 4; u++) {            // K hi, V hi: tile 0
        int r = (u & 1) * 32 + cr;
        const char* tp = (u < 2) ? khc : vhc;
        const char* src = tp + (size_t)r * rowb + qko * 2 + ch * 16;
        cpa16(sb + ABUF0 + (u >> 1) * KVT + (uint32_t)r * ASTR + ch * 16, src);
    }
    CP_COMMIT();
    CP_WAIT0();
    __syncthreads();

    const int blk = lane >> 3, lr = lane & 7;
    uint32_t qfh[4][4], qfl[4][4];
    {
        uint32_t qa = sb + (uint32_t)(w * 16 + (blk & 1) * 8 + lr) * ASTR + (uint32_t)(blk >> 1) * 16;
        #pragma unroll
        for (int ks = 0; ks < 4; ks++) {
            ldsm_x4(qa + ks * 32,        qfh[ks][0], qfh[ks][1], qfh[ks][2], qfh[ks][3]);
            ldsm_x4(qa + QLSM + ks * 32, qfl[ks][0], qfl[ks][1], qfl[ks][2], qfl[ks][3]);
        }
    }

    float O[8][4];
    #pragma unroll
    for (int nf = 0; nf < 8; nf++)
        #pragma unroll
        for (int r = 0; r < 4; r++) O[nf][r] = 0.f;
    float l0 = 0.f, l1 = 0.f;

    const int nk = 2 * qt + 2;
    const int r0g = q0 + w * 16 + g;
    const uint32_t ldsmV_off = (uint32_t)((blk & 1) * 8 + lr) * ASTR + (uint32_t)(blk >> 1) * 16;
    const uint32_t ldsmK_off = (uint32_t)(((lane >> 4) << 3) | lr) * ASTR + (uint32_t)((blk & 1) * 16);

    for (int kt = 0; kt < nk; kt++) {
        const uint32_t kb = ABUF0 + (uint32_t)(kt & 1) * ABUFB;
        const bool more = (kt + 1 < nk);

        if (more) {
            int k0n = (kt + 1) * 64;
            uint32_t nb = sb + ABUF0 + (uint32_t)((kt + 1) & 1) * ABUFB;
            #pragma unroll
            for (int u = 0; u < 4; u++) {
                int r = (u & 1) * 32 + cr;
                const char* tp = (u < 2) ? khc : vhc;
                const char* src = tp + (size_t)(k0n + r) * rowb + qko * 2 + ch * 16;
                cpa16(nb + (u >> 1) * KVT + (uint32_t)r * ASTR + ch * 16, src);
            }
            CP_COMMIT();
        }

        float S[8][4];
        #pragma unroll
        for (int nf = 0; nf < 8; nf++)
            #pragma unroll
            for (int r = 0; r < 4; r++) S[nf][r] = 0.f;

        {
            const uint32_t kh = sb + kb + ldsmK_off;
            #pragma unroll
            for (int ks = 0; ks < 4; ks++) {
                #pragma unroll
                for (int nfp = 0; nfp < 4; nfp++) {
                    uint32_t a = kh + (uint32_t)(nfp * 16) * ASTR + (uint32_t)(ks * 32);
                    uint32_t h0, h1, h2, h3;
                    ldsm_x4(a, h0, h1, h2, h3);
                    uint32_t bh0[2] = {h0, h1}, bh1[2] = {h2, h3};
                    mma_bf16(S[2 * nfp],     qfh[ks], bh0);
                    mma_bf16(S[2 * nfp],     qfl[ks], bh0);
                    mma_bf16(S[2 * nfp + 1], qfh[ks], bh1);
                    mma_bf16(S[2 * nfp + 1], qfl[ks], bh1);
                }
            }
        }

        if (kt >= 2 * qt) {
            int k0 = kt * 64;
            #pragma unroll
            for (int nf = 0; nf < 8; nf++) {
                int c = k0 + nf * 8 + 2 * t;
                if (c     > r0g)     S[nf][0] = -1e30f;
                if (c + 1 > r0g)     S[nf][1] = -1e30f;
                if (c     > r0g + 8) S[nf][2] = -1e30f;
                if (c + 1 > r0g + 8) S[nf][3] = -1e30f;
            }
        }

        #pragma unroll
        for (int nf = 0; nf < 8; nf++) {
            S[nf][0] = ex2(S[nf][0]);
            S[nf][1] = ex2(S[nf][1]);
            S[nf][2] = ex2(S[nf][2]);
            S[nf][3] = ex2(S[nf][3]);
            l0 += S[nf][0] + S[nf][1];
            l1 += S[nf][2] + S[nf][3];
        }

        {
            const uint32_t vh = sb + kb + KVT + ldsmV_off;
            #pragma unroll
            for (int ks = 0; ks < 4; ks++) {
                float p00 = S[2 * ks][0], p01 = S[2 * ks][1];
                float p02 = S[2 * ks][2], p03 = S[2 * ks][3];
                float p10 = S[2 * ks + 1][0], p11 = S[2 * ks + 1][1];
                float p12 = S[2 * ks + 1][2], p13 = S[2 * ks + 1][3];
                uint32_t pah[4], pal[4];
                pah[0] = cvt2(p00, p01);
                pah[1] = cvt2(p02, p03);
                pah[2] = cvt2(p10, p11);
                pah[3] = cvt2(p12, p13);
                pal[0] = cvt2(p00 - __uint_as_float(pah[0] << 16),
                              p01 - __uint_as_float(pah[0] & 0xFFFF0000u));
                pal[1] = cvt2(p02 - __uint_as_float(pah[1] << 16),
                              p03 - __uint_as_float(pah[1] & 0xFFFF0000u));
                pal[2] = cvt2(p10 - __uint_as_float(pah[2] << 16),
                              p11 - __uint_as_float(pah[2] & 0xFFFF0000u));
                pal[3] = cvt2(p12 - __uint_as_float(pah[3] << 16),
                              p13 - __uint_as_float(pah[3] & 0xFFFF0000u));

                uint32_t ka = vh + (uint32_t)(ks * 16) * ASTR;
                #pragma unroll
                for (int np = 0; np < 4; np++) {
                    uint32_t a = ka + (uint32_t)np * 32;
                    uint32_t b0, b1, b2, b3;
                    ldsm_x4_trans(a, b0, b1, b2, b3);
                    uint32_t bb0[2] = {b0, b1}, bb1[2] = {b2, b3};
                    mma_bf16(O[2 * np],     pah, bb0);
                    mma_bf16(O[2 * np],     pal, bb0);
                    mma_bf16(O[2 * np + 1], pah, bb1);
                    mma_bf16(O[2 * np + 1], pal, bb1);
                }
            }
        }

        if (more) CP_WAIT0();
        __syncthreads();
    }

    // ---- epilogue: write y as bf16 hi/lo
    l0 += __shfl_xor_sync(0xFFFFFFFFu, l0, 1);
    l0 += __shfl_xor_sync(0xFFFFFFFFu, l0, 2);
    l1 += __shfl_xor_sync(0xFFFFFFFFu, l1, 1);
    l1 += __shfl_xor_sync(0xFFFFFFFFu, l1, 2);
    float i0 = 1.f / l0, i1 = 1.f / l1;
    #pragma unroll
    for (int nf = 0; nf < 8; nf++) {
        int cp = (qko >> 1) + nf * 4 + t;
        float o0 = O[nf][0] * i0, o1 = O[nf][1] * i0;
        float o2 = O[nf][2] * i1, o3 = O[nf][3] * i1;
        uint32_t h0 = cvt2(o0, o1);
        uint32_t l0w = cvt2(o0 - __uint_as_float(h0 << 16),
                            o1 - __uint_as_float(h0 & 0xFFFF0000u));
        uint32_t h1 = cvt2(o2, o3);
        uint32_t l1w = cvt2(o2 - __uint_as_float(h1 << 16),
                            o3 - __uint_as_float(h1 & 0xFFFF0000u));
        yh[(size_t)r0g * 512 + cp]       = h0;
        yl[(size_t)r0g * 512 + cp]       = l0w;
        yh[(size_t)(r0g + 8) * 512 + cp] = h1;
        yl[(size_t)(r0g + 8) * 512 + cp] = l1w;
    }
}

// ---------------- launch ----------------
extern "C" void kernel_launch(void* const* d_in, const int* in_sizes, int n_in,
                              void* d_out, int out_size) {
    const float* x           = (const float*)d_in[0];
    const float* attn_norm_w = (const float*)d_in[1];
    const float* ffn_norm_w  = (const float*)d_in[2];
    const float* c_attn_w    = (const float*)d_in[3];
    const float* c_proj_w    = (const float*)d_in[4];
    const float* w1          = (const float*)d_in[5];
    const float* w2          = (const float*)d_in[6];
    const float* w3          = (const float*)d_in[7];
    float* out = (float*)d_out;

    float *x1, *h1, *h3;
    cudaGetSymbolAddress((void**)&x1,  g_x1);
    cudaGetSymbolAddress((void**)&h1,  g_h1);
    cudaGetSymbolAddress((void**)&h3,  g_h3);
    void *qh, *ql, *kh, *vh, *whv, *wlv, *axh, *axl, *hh, *hl;
    cudaGetSymbolAddress(&qh, g_qh);
    cudaGetSymbolAddress(&ql, g_ql);
    cudaGetSymbolAddress(&kh, g_kh);
    cudaGetSymbolAddress(&vh, g_vh);
    cudaGetSymbolAddress(&whv, g_wh);
    cudaGetSymbolAddress(&wlv, g_wl);
    cudaGetSymbolAddress(&axh, g_axh);
    cudaGetSymbolAddress(&axl, g_axl);
    cudaGetSymbolAddress(&hh, g_hh);
    cudaGetSymbolAddress(&hl, g_hl);

    const char* whc = (const char*)whv;
    const char* wlc = (const char*)wlv;

    cudaFuncSetAttribute(gemm_pre<false>, cudaFuncAttributeMaxDynamicSharedMemorySize, GEMM_SMEM);
    cudaFuncSetAttribute(gemm_pre<true>,  cudaFuncAttributeMaxDynamicSharedMemorySize, GEMM_SMEM);
    cudaFuncSetAttribute(attn_mma, cudaFuncAttributeMaxDynamicSharedMemorySize, ATTN_SMEM);

    // 0) split all weights into bf16 hi/lo (single launch)
    split_weights<<<(int)(NWELEM / 4 / 256), 256>>>(
        (const float4*)c_attn_w, (const float4*)c_proj_w,
        (const float4*)w1, (const float4*)w3, (const float4*)w2,
        (uint2*)whv, (uint2*)wlv);

    // 1) xn = rmsnorm(x, attn_norm_w) -> bf16 hi/lo
    rmsnorm_split<<<TT, 256>>>(x, attn_norm_w, (uint2*)axh, (uint2*)axl);

    // 2) qkv GEMM -> Q hi+lo (scaled), K hi, V hi
    gemm_pre<true><<<dim3(3 * CC / 128, TT / 128), 256, GEMM_SMEM>>>(
        (const char*)axh, (const char*)axl,
        whc + OFF_CATTN * 2, wlc + OFF_CATTN * 2, nullptr, TT, 3 * CC, CC, nullptr,
        (uint32_t*)qh, (uint32_t*)ql, (uint32_t*)kh, (uint32_t*)vh);

    // 3) y = causal_attention -> split bf16 y (into ax buffers)
    attn_mma<<<dim3(TT / 128, NH), 256, ATTN_SMEM>>>(
        (const char*)qh, (const char*)ql, (const char*)kh, (const char*)vh,
        (uint32_t*)axh, (uint32_t*)axl);

    // 4) x1 = y @ c_proj_w^T + x
    gemm_pre<false><<<dim3(CC / 128, TT / 128), 256, GEMM_SMEM>>>(
        (const char*)axh, (const char*)axl,
        whc + OFF_CPROJ * 2, wlc + OFF_CPROJ * 2, x1, TT, CC, CC, x,
        nullptr, nullptr, nullptr, nullptr);

    // 5) xn = rmsnorm(x1, ffn_norm_w) -> bf16 hi/lo
    rmsnorm_split<<<TT, 256>>>(x1, ffn_norm_w, (uint2*)axh, (uint2*)axl);

    // 6) h1 = xn @ w1^T ; h3 = xn @ w3^T
    gemm_pre<false><<<dim3(HF / 128, TT / 128), 256, GEMM_SMEM>>>(
        (const char*)axh, (const char*)axl,
        whc + OFF_W1 * 2, wlc + OFF_W1 * 2, h1, TT, HF, CC, nullptr,
        nullptr, nullptr, nullptr, nullptr);
    gemm_pre<false><<<dim3(HF / 128, TT / 128), 256, GEMM_SMEM>>>(
        (const char*)axh, (const char*)axl,
        whc + OFF_W3 * 2, wlc + OFF_W3 * 2, h3, TT, HF, CC, nullptr,
        nullptr, nullptr, nullptr, nullptr);

    // 7) h = silu(h1) * h3, split output
    swiglu_split<<<(TT * HF / 4) / 256, 256>>>((const float4*)h1, (const float4*)h3,
                                               (uint2*)hh, (uint2*)hl, TT * HF / 4);

    // 8) out = h @ w2^T + x1
    gemm_pre<false><<<dim3(CC / 128, TT / 128), 256, GEMM_SMEM>>>(
        (const char*)hh, (const char*)hl,
        whc + OFF_W2 * 2, wlc + OFF_W2 * 2, out, TT, CC, HF, x1,
        nullptr, nullptr, nullptr, nullptr);
}